// round 6
// baseline (speedup 1.0000x reference)
#include <cuda_runtime.h>
#include <cuda_bf16.h>
#include <cstdint>

#define E_TOTAL 160000
#define NNODES  10000
#define NBLK    1250

#define SP   136                 // padded row stride (bf16 elems)
#define SPB  272                 // row stride bytes
#define BUF  (128 * SPB)         // 34816 bytes: one 128x136 bf16 buffer

// ---------------- SMEM layout (bytes) ----------------
#define AB_OFF 0                 // A operand: hi @ +0, lo @ +BUF   (EA tile, later H tile)
#define WB_OFF (2 * BUF)         // B operand: hi @ +0, lo @ +BUF   (W1T, later W2T chunks)
#define FL_OFF (4 * BUF)         // float region
#define SA0  0                   // x0*sh0      [128][16]
#define SA1  2048                // x0          [128][16]
#define SA3  4096                // dot/sqrt3   [128][16]
#define SX1  6144                // x1          [128][48]
#define SSH  12288               // sh          [128][4]
#define SDST 12800               // int [128]
#define SSRC 12928               // int [128]
#define SB1  13056               // b1 [128]
#define SB2  13184               // b2 [1024]
#define NFL  14208
#define SMEM_BYTES (FL_OFF + NFL * 4)   // 196096

__device__ float g_acc[NNODES * 64];
__device__ float g_cnt[NNODES];
__device__ __align__(16) unsigned char g_w1s[2 * BUF];       // W1T hi + lo
__device__ __align__(16) unsigned char g_w2s[8][2 * BUF];    // per N-chunk W2T hi + lo

// ---------------- helpers ----------------
__device__ __forceinline__ uint32_t smem_u32(const void* p) {
    uint32_t a;
    asm("{ .reg .u64 t; cvta.to.shared.u64 t, %1; cvt.u32.u64 %0, t; }" : "=r"(a) : "l"(p));
    return a;
}
__device__ __forceinline__ void ldsm_x4(uint32_t* r, uint32_t addr) {
    asm volatile("ldmatrix.sync.aligned.m8n8.x4.shared.b16 {%0,%1,%2,%3}, [%4];"
        : "=r"(r[0]), "=r"(r[1]), "=r"(r[2]), "=r"(r[3]) : "r"(addr));
}
__device__ __forceinline__ void mma16816(float* c, const uint32_t* a, const uint32_t* b) {
    asm volatile("mma.sync.aligned.m16n8k16.row.col.f32.bf16.bf16.f32 "
        "{%0,%1,%2,%3}, {%4,%5,%6,%7}, {%8,%9}, {%0,%1,%2,%3};"
        : "+f"(c[0]), "+f"(c[1]), "+f"(c[2]), "+f"(c[3])
        : "r"(a[0]), "r"(a[1]), "r"(a[2]), "r"(a[3]), "r"(b[0]), "r"(b[1]));
}
__device__ __forceinline__ uint32_t pk(float a, float b) {
    uint32_t ua = __bfloat16_as_ushort(__float2bfloat16_rn(a));
    uint32_t ub = __bfloat16_as_ushort(__float2bfloat16_rn(b));
    return ua | (ub << 16);
}
__device__ __forceinline__ float blo(float a) {
    return a - __bfloat162float(__float2bfloat16_rn(a));
}

// m16 x n64 x k128 slice of the 3-pass bf16 compensated GEMM.
// acc += Ah*Bh + Ah*Bl + Al*Bh.  A row-major [m][k], B n-major [n][k].
__device__ __forceinline__ void gemm3(float acc[8][4],
                                      uint32_t a_hi, uint32_t a_lo,
                                      uint32_t w_hi, uint32_t w_lo,
                                      uint32_t aoff, uint32_t boff) {
    #pragma unroll
    for (int kp = 0; kp < 4; kp++) {        // k32 per iteration
        uint32_t Ah[2][4], Al[2][4];
        ldsm_x4(Ah[0], a_hi + aoff + kp * 64);
        ldsm_x4(Ah[1], a_hi + aoff + kp * 64 + 32);
        ldsm_x4(Al[0], a_lo + aoff + kp * 64);
        ldsm_x4(Al[1], a_lo + aoff + kp * 64 + 32);
        #pragma unroll
        for (int nt = 0; nt < 8; nt++) {
            uint32_t Bh[4], Bl[4];
            uint32_t wb = (uint32_t)nt * (8 * SPB) + boff + kp * 64;
            ldsm_x4(Bh, w_hi + wb);
            ldsm_x4(Bl, w_lo + wb);
            mma16816(acc[nt], Ah[0], Bh);     mma16816(acc[nt], Ah[1], Bh + 2);
            mma16816(acc[nt], Ah[0], Bl);     mma16816(acc[nt], Ah[1], Bl + 2);
            mma16816(acc[nt], Al[0], Bh);     mma16816(acc[nt], Al[1], Bh + 2);
        }
    }
}

// ---------------- small kernels ----------------
__global__ void zero_kernel() {
    int i = blockIdx.x * blockDim.x + threadIdx.x;
    if (i < NNODES * 64) g_acc[i] = 0.0f;
    else if (i < NNODES * 64 + NNODES) g_cnt[i - NNODES * 64] = 0.0f;
}

__global__ void prep_w1(const float* __restrict__ w1) {
    int t = blockIdx.x * 256 + threadIdx.x;
    if (t >= 128 * 64) return;
    int h = t >> 6, f = (t & 63) * 2;
    float v0 = w1[f * 128 + h], v1 = w1[(f + 1) * 128 + h];
    uint32_t off = (uint32_t)h * SPB + (uint32_t)f * 2;
    *(uint32_t*)(g_w1s + off)       = pk(v0, v1);
    *(uint32_t*)(g_w1s + BUF + off) = pk(blo(v0), blo(v1));
}

__global__ void prep_w2(const float* __restrict__ w2) {
    int t = blockIdx.x * 256 + threadIdx.x;
    if (t >= 8 * 128 * 64) return;
    int c = t >> 13, n = (t >> 6) & 127, f = (t & 63) * 2;
    int kg = c * 128 + n;
    float v0 = w2[f * 1024 + kg], v1 = w2[(f + 1) * 1024 + kg];
    uint32_t off = (uint32_t)n * SPB + (uint32_t)f * 2;
    *(uint32_t*)(g_w2s[c] + off)       = pk(v0, v1);
    *(uint32_t*)(g_w2s[c] + BUF + off) = pk(blo(v0), blo(v1));
}

// ---------------- main fused kernel: 512 threads, 8m x 2n warp grid ----------------
__global__ void __launch_bounds__(512, 1) fused_kernel(
    const float* __restrict__ x,  const int* __restrict__ ei,
    const float* __restrict__ ea, const float* __restrict__ esh,
    const float* __restrict__ b1, const float* __restrict__ b2)
{
    extern __shared__ unsigned char sm[];
    unsigned char* ABc = sm + AB_OFF;
    float* F   = (float*)(sm + FL_OFF);
    float* Sa0 = F + SA0;
    float* Sa1 = F + SA1;
    float* Sa3 = F + SA3;
    float* Sx1 = F + SX1;
    float* Ssh = F + SSH;
    int* Sdst  = (int*)(F + SDST);
    int* Ssrc  = (int*)(F + SSRC);
    float* b1s = F + SB1;
    float* b2s = F + SB2;

    const int tid = threadIdx.x;
    const int wid = tid >> 5, lid = tid & 31;
    const int e0  = blockIdx.x * 128;
    const uint32_t sb = smem_u32(sm);

    // warp tile geometry: 8 m-blocks x 2 n-halves
    const int m0 = (wid & 7) * 16;
    const int nh = wid >> 3;                       // 0 or 1
    const int r0 = m0 + (lid >> 2), r1 = r0 + 8;   // the two edge-rows this thread owns
    const int cb = (lid & 3) * 2;                  // base col within n8 tile
    const uint32_t aoff = (uint32_t)(m0 + (lid & 15)) * SPB + (uint32_t)((lid >> 4) * 8) * 2;
    const uint32_t boff = (uint32_t)(nh * 64 + (lid & 7)) * SPB + (uint32_t)(lid >> 3) * 16;

    // ---- stage biases ----
    if (tid < 128) b1s[tid] = b1[tid];
    b2s[tid]       = b2[tid];
    b2s[tid + 512] = b2[tid + 512];

    // ---- phase 1: indices + sh ----
    if (tid < 128) {
        int eg = e0 + tid;
        Ssrc[tid] = ei[eg];
        Sdst[tid] = ei[E_TOTAL + eg];
        float4 s = *(const float4*)(esh + (size_t)eg * 4);
        Ssh[tid*4+0] = s.x; Ssh[tid*4+1] = s.y; Ssh[tid*4+2] = s.z; Ssh[tid*4+3] = s.w;
    }
    __syncthreads();

    // ---- phase 2: gather x[src] + TP precompute (256 threads) ----
    if (tid < 256) {
        int e = tid & 127, part = tid >> 7;
        int src = Ssrc[e];
        const float4* xr = (const float4*)(x + (size_t)src * 64);
        if (part == 0) {
            float sh0 = Ssh[e*4];
            #pragma unroll
            for (int q = 0; q < 4; q++) {
                float4 xv = xr[q];
                int u = q * 4;
                Sa1[e*16+u+0] = xv.x;  Sa0[e*16+u+0] = xv.x * sh0;
                Sa1[e*16+u+1] = xv.y;  Sa0[e*16+u+1] = xv.y * sh0;
                Sa1[e*16+u+2] = xv.z;  Sa0[e*16+u+2] = xv.z * sh0;
                Sa1[e*16+u+3] = xv.w;  Sa0[e*16+u+3] = xv.w * sh0;
            }
        } else {
            float s1x = Ssh[e*4+1], s1y = Ssh[e*4+2], s1z = Ssh[e*4+3];
            float x1l[48];
            #pragma unroll
            for (int q = 0; q < 12; q++) {
                float4 xv = xr[4 + q];
                x1l[q*4+0]=xv.x; x1l[q*4+1]=xv.y; x1l[q*4+2]=xv.z; x1l[q*4+3]=xv.w;
                *(float4*)(Sx1 + e*48 + q*4) = xv;
            }
            #pragma unroll
            for (int u = 0; u < 16; u++) {
                float d = x1l[u*3]*s1x + x1l[u*3+1]*s1y + x1l[u*3+2]*s1z;
                Sa3[e*16+u] = d * 0.57735026918962576f;
            }
        }
    }

    // ---- EA tile -> bf16 hi/lo into A buffer (512 threads: 1/4 row each) ----
    {
        int r = tid >> 2, q = tid & 3;
        const float4* rowp = (const float4*)(ea + (size_t)(e0 + r) * 128 + q * 32);
        #pragma unroll
        for (int j = 0; j < 8; j++) {
            float4 v = rowp[j];
            int k = q * 32 + j * 4;
            uint32_t* hi = (uint32_t*)(ABc + (uint32_t)r * SPB + (uint32_t)k * 2);
            uint32_t* lo = (uint32_t*)(ABc + BUF + (uint32_t)r * SPB + (uint32_t)k * 2);
            hi[0] = pk(v.x, v.y);           hi[1] = pk(v.z, v.w);
            lo[0] = pk(blo(v.x), blo(v.y)); lo[1] = pk(blo(v.z), blo(v.w));
        }
    }
    // ---- stage W1 (68KB flat) ----
    {
        const float4* src = (const float4*)g_w1s;
        float4* dst = (float4*)(sm + WB_OFF);
        #pragma unroll
        for (int i = 0; i < 9; i++) {
            int idx = tid + i * 512;
            if (idx < (2 * BUF) / 16) dst[idx] = src[idx];
        }
    }
    __syncthreads();

    // ---- GEMM1: H = relu(EA @ W1 + b1) ----
    float acc[8][4];
    #pragma unroll
    for (int nt = 0; nt < 8; nt++)
        #pragma unroll
        for (int q = 0; q < 4; q++) acc[nt][q] = 0.0f;

    gemm3(acc, sb + AB_OFF, sb + AB_OFF + BUF, sb + WB_OFF, sb + WB_OFF + BUF, aoff, boff);
    __syncthreads();   // all warps done reading EA from A buffer

    // writeback H (bias+relu) as bf16 hi/lo into A buffer (cols nh*64 + nt*8 + cb)
    #pragma unroll
    for (int nt = 0; nt < 8; nt++) {
        int c = nh * 64 + nt * 8 + cb;
        float h0 = fmaxf(acc[nt][0] + b1s[c],     0.0f);
        float h1 = fmaxf(acc[nt][1] + b1s[c + 1], 0.0f);
        float h2 = fmaxf(acc[nt][2] + b1s[c],     0.0f);
        float h3 = fmaxf(acc[nt][3] + b1s[c + 1], 0.0f);
        *(uint32_t*)(ABc + (uint32_t)r0 * SPB + (uint32_t)c * 2)       = pk(h0, h1);
        *(uint32_t*)(ABc + BUF + (uint32_t)r0 * SPB + (uint32_t)c * 2) = pk(blo(h0), blo(h1));
        *(uint32_t*)(ABc + (uint32_t)r1 * SPB + (uint32_t)c * 2)       = pk(h2, h3);
        *(uint32_t*)(ABc + BUF + (uint32_t)r1 * SPB + (uint32_t)c * 2) = pk(blo(h2), blo(h3));
    }

    // ---- GEMM2 chunks + TP consumption ----
    float s0[2][4], t1[2][4], o1[2][4][3];
    #pragma unroll
    for (int rr = 0; rr < 2; rr++)
        #pragma unroll
        for (int vi = 0; vi < 4; vi++) {
            s0[rr][vi] = 0.0f; t1[rr][vi] = 0.0f;
            o1[rr][vi][0] = 0.0f; o1[rr][vi][1] = 0.0f; o1[rr][vi][2] = 0.0f;
        }

    #pragma unroll 1
    for (int ch = 0; ch < 8; ch++) {
        __syncthreads();   // prior W-buffer reads complete (and H writes on first iter)
        {
            const float4* src = (const float4*)(g_w2s[ch]);
            float4* dst = (float4*)(sm + WB_OFF);
            #pragma unroll
            for (int i = 0; i < 9; i++) {
                int idx = tid + i * 512;
                if (idx < (2 * BUF) / 16) dst[idx] = src[idx];
            }
        }
        __syncthreads();

        #pragma unroll
        for (int nt = 0; nt < 8; nt++)
            #pragma unroll
            for (int q = 0; q < 4; q++) acc[nt][q] = 0.0f;

        gemm3(acc, sb + AB_OFF, sb + AB_OFF + BUF, sb + WB_OFF, sb + WB_OFF + BUF, aoff, boff);

        // epilogue: consume chunk into TP register accumulators.
        // global col k = ch*128 + nh*64 + nt*8 + cb + d ; p = ch>>1 ;
        // u = (ch&1)*8 + nh*4 + nt/2 ; v = (nt*8 + cb + d) & 15
        const int p  = ch >> 1;
        const int ub = (ch & 1) * 8 + nh * 4;
        const float* b2c = b2s + ch * 128 + nh * 64;

        if (p == 2) {
            #pragma unroll
            for (int nt = 0; nt < 8; nt++) {
                int u = ub + (nt >> 1);
                float xa0 = Sx1[r0*48 + u*3 + 0], xb0 = Sx1[r0*48 + u*3 + 1], xc0 = Sx1[r0*48 + u*3 + 2];
                float xa1 = Sx1[r1*48 + u*3 + 0], xb1 = Sx1[r1*48 + u*3 + 1], xc1 = Sx1[r1*48 + u*3 + 2];
                #pragma unroll
                for (int d = 0; d < 2; d++) {
                    float bb = b2c[nt*8 + cb + d];
                    int vi = (nt & 1) * 2 + d;
                    float w0 = acc[nt][d]     + bb;
                    float w1 = acc[nt][2 + d] + bb;
                    o1[0][vi][0] = fmaf(xa0, w0, o1[0][vi][0]);
                    o1[0][vi][1] = fmaf(xb0, w0, o1[0][vi][1]);
                    o1[0][vi][2] = fmaf(xc0, w0, o1[0][vi][2]);
                    o1[1][vi][0] = fmaf(xa1, w1, o1[1][vi][0]);
                    o1[1][vi][1] = fmaf(xb1, w1, o1[1][vi][1]);
                    o1[1][vi][2] = fmaf(xc1, w1, o1[1][vi][2]);
                }
            }
        } else {
            const float* A = (p == 0) ? Sa0 : (p == 1) ? Sa1 : Sa3;
            float a0[4], a1[4];
            #pragma unroll
            for (int u = 0; u < 4; u++) {
                a0[u] = A[r0*16 + ub + u];
                a1[u] = A[r1*16 + ub + u];
            }
            if (p == 1) {
                #pragma unroll
                for (int nt = 0; nt < 8; nt++) {
                    int u = nt >> 1;
                    #pragma unroll
                    for (int d = 0; d < 2; d++) {
                        float bb = b2c[nt*8 + cb + d];
                        int vi = (nt & 1) * 2 + d;
                        t1[0][vi] = fmaf(a0[u], acc[nt][d]     + bb, t1[0][vi]);
                        t1[1][vi] = fmaf(a1[u], acc[nt][2 + d] + bb, t1[1][vi]);
                    }
                }
            } else {
                #pragma unroll
                for (int nt = 0; nt < 8; nt++) {
                    int u = nt >> 1;
                    #pragma unroll
                    for (int d = 0; d < 2; d++) {
                        float bb = b2c[nt*8 + cb + d];
                        int vi = (nt & 1) * 2 + d;
                        s0[0][vi] = fmaf(a0[u], acc[nt][d]     + bb, s0[0][vi]);
                        s0[1][vi] = fmaf(a1[u], acc[nt][2 + d] + bb, s0[1][vi]);
                    }
                }
            }
        }
    }

    // ---- scatter-add (two warps per edge-row merge via atomics) ----
    {
        const float alpha = 0.17677669529663689f;  // 1/sqrt(2*16)
        #pragma unroll
        for (int rr = 0; rr < 2; rr++) {
            int e = rr ? r1 : r0;
            int dst = Sdst[e];
            float sh0 = Ssh[e*4+0];
            float s1x = Ssh[e*4+1], s1y = Ssh[e*4+2], s1z = Ssh[e*4+3];
            float* base = g_acc + (size_t)dst * 64;
            #pragma unroll
            for (int vi = 0; vi < 4; vi++) {
                int v = cb + (vi >> 1) * 8 + (vi & 1);
                atomicAdd(base + v, alpha * s0[rr][vi]);
                atomicAdd(base + 16 + v*3 + 0, alpha * (t1[rr][vi]*s1x + sh0*o1[rr][vi][0]));
                atomicAdd(base + 16 + v*3 + 1, alpha * (t1[rr][vi]*s1y + sh0*o1[rr][vi][1]));
                atomicAdd(base + 16 + v*3 + 2, alpha * (t1[rr][vi]*s1z + sh0*o1[rr][vi][2]));
            }
            if ((lid & 3) == 0 && nh == 0) atomicAdd(&g_cnt[dst], 1.0f);
        }
    }
}

__global__ void finalize_kernel(const float* __restrict__ x, float* __restrict__ out) {
    int i = blockIdx.x * blockDim.x + threadIdx.x;
    if (i < NNODES * 64) {
        int node = i >> 6;
        out[i] = g_acc[i] / fmaxf(g_cnt[node], 1.0f) + x[i];
    }
}

extern "C" void kernel_launch(void* const* d_in, const int* in_sizes, int n_in,
                              void* d_out, int out_size)
{
    const float* x   = (const float*)d_in[0];
    const int*   ei  = (const int*)  d_in[1];
    const float* ea  = (const float*)d_in[2];
    const float* esh = (const float*)d_in[3];
    const float* w1  = (const float*)d_in[4];
    const float* b1  = (const float*)d_in[5];
    const float* w2  = (const float*)d_in[6];
    const float* b2  = (const float*)d_in[7];
    float* out = (float*)d_out;

    cudaFuncSetAttribute(fused_kernel,
                         cudaFuncAttributeMaxDynamicSharedMemorySize, SMEM_BYTES);

    int ztot = NNODES * 64 + NNODES;
    zero_kernel<<<(ztot + 255) / 256, 256>>>();
    prep_w1<<<(128 * 64 + 255) / 256, 256>>>(w1);
    prep_w2<<<(8 * 128 * 64 + 255) / 256, 256>>>(w2);
    fused_kernel<<<NBLK, 512, SMEM_BYTES>>>(x, ei, ea, esh, b1, b2);
    finalize_kernel<<<(NNODES * 64 + 255) / 256, 256>>>(x, out);
}

// round 8
// speedup vs baseline: 1.4727x; 1.4727x over previous
#include <cuda_runtime.h>
#include <cuda_fp16.h>
#include <cstdint>

#define E_TOTAL 160000
#define NNODES  10000
#define NBLK    1250

#define SP   136                 // padded row stride (fp16 elems)
#define SPB  272                 // row stride bytes
#define BUF  (128 * SPB)         // 34816 B: one 128x136 fp16 buffer
#define WCH  (2 * BUF)           // 69632 B: hi+lo weight chunk

// ---------------- SMEM layout (bytes) ----------------
#define AB_OFF  0                // A operand fp16 (EA tile, later H tile)
#define WB0_OFF BUF              // weight buffer 0 (hi @ +0, lo @ +BUF)
#define WB1_OFF (BUF + WCH)      // weight buffer 1
#define FL_OFF  (BUF + 2 * WCH)  // 174080: float region
#define SA0  0                   // x0*sh0      [128][16]
#define SA1  2048                // x0          [128][16]
#define SA3  4096                // dot/sqrt3   [128][16]
#define SX1  6144                // x1          [128][48]
#define SSH  12288               // sh          [128][4]
#define SDST 12800               // int [128]
#define SSRC 12928               // int [128]
#define SB1  13056               // b1 [128]
#define SB2  13184               // b2 [1024]
#define NFL  14208
#define SMEM_BYTES (FL_OFF + NFL * 4)   // 230912
#define MG_OFF  WB0_OFF          // merge buffer aliases weight bufs after last gemm

#define WSCALE 256.0f
#define INV_S  (1.0f / 256.0f)

__device__ float g_acc[NNODES * 64];
__device__ float g_cnt[NNODES];
__device__ __align__(16) unsigned char g_w1s[WCH];       // W1T hi+lo, scaled
__device__ __align__(16) unsigned char g_w2s[8][WCH];    // per N-chunk W2T hi+lo, scaled

// ---------------- helpers ----------------
__device__ __forceinline__ uint32_t smem_u32(const void* p) {
    uint32_t a;
    asm("{ .reg .u64 t; cvta.to.shared.u64 t, %1; cvt.u32.u64 %0, t; }" : "=r"(a) : "l"(p));
    return a;
}
__device__ __forceinline__ void ldsm_x4(uint32_t* r, uint32_t addr) {
    asm volatile("ldmatrix.sync.aligned.m8n8.x4.shared.b16 {%0,%1,%2,%3}, [%4];"
        : "=r"(r[0]), "=r"(r[1]), "=r"(r[2]), "=r"(r[3]) : "r"(addr));
}
__device__ __forceinline__ void mma16816(float* c, const uint32_t* a, const uint32_t* b) {
    asm volatile("mma.sync.aligned.m16n8k16.row.col.f32.f16.f16.f32 "
        "{%0,%1,%2,%3}, {%4,%5,%6,%7}, {%8,%9}, {%0,%1,%2,%3};"
        : "+f"(c[0]), "+f"(c[1]), "+f"(c[2]), "+f"(c[3])
        : "r"(a[0]), "r"(a[1]), "r"(a[2]), "r"(a[3]), "r"(b[0]), "r"(b[1]));
}
__device__ __forceinline__ uint32_t pkh(float a, float b) {
    __half2 h = __floats2half2_rn(a, b);
    return *(uint32_t*)&h;
}
__device__ __forceinline__ void cp16(uint32_t dst, const void* src) {
    asm volatile("cp.async.cg.shared.global [%0], [%1], 16;" :: "r"(dst), "l"(src));
}
#define CP_COMMIT() asm volatile("cp.async.commit_group;" ::: "memory")
#define CP_WAIT(n)  asm volatile("cp.async.wait_group %0;" :: "n"(n) : "memory")

// warp tile m32 x n64, k128, 2-pass (B hi + lo compensated, A single fp16).
__device__ __forceinline__ void gemm2p(float acc[2][8][4],
                                       uint32_t a_base, uint32_t w_base,
                                       uint32_t aoff, uint32_t boff) {
    #pragma unroll
    for (int kp = 0; kp < 4; kp++) {        // k32 per iteration
        uint32_t Am[2][8];                  // per m16 tile: [0..3]=k16lo frag, [4..7]=k16hi frag
        ldsm_x4(Am[0],     a_base + aoff + kp * 64);
        ldsm_x4(Am[0] + 4, a_base + aoff + kp * 64 + 32);
        ldsm_x4(Am[1],     a_base + aoff + 16 * SPB + kp * 64);
        ldsm_x4(Am[1] + 4, a_base + aoff + 16 * SPB + kp * 64 + 32);
        #pragma unroll
        for (int nt = 0; nt < 8; nt++) {
            uint32_t Bh[4], Bl[4];
            uint32_t wb = (uint32_t)nt * (8 * SPB) + boff + kp * 64;
            ldsm_x4(Bh, w_base + wb);
            ldsm_x4(Bl, w_base + BUF + wb);
            #pragma unroll
            for (int mt = 0; mt < 2; mt++) {
                mma16816(acc[mt][nt], Am[mt],     Bh);
                mma16816(acc[mt][nt], Am[mt] + 4, Bh + 2);
                mma16816(acc[mt][nt], Am[mt],     Bl);
                mma16816(acc[mt][nt], Am[mt] + 4, Bl + 2);
            }
        }
    }
}

// ---------------- small kernels ----------------
__global__ void zero_kernel() {
    int i = blockIdx.x * blockDim.x + threadIdx.x;
    if (i < NNODES * 64) g_acc[i] = 0.0f;
    else if (i < NNODES * 64 + NNODES) g_cnt[i - NNODES * 64] = 0.0f;
}

__global__ void prep_w1(const float* __restrict__ w1) {
    int t = blockIdx.x * 256 + threadIdx.x;
    if (t >= 128 * 64) return;
    int h = t >> 6, f = (t & 63) * 2;
    float v0 = w1[f * 128 + h] * WSCALE, v1 = w1[(f + 1) * 128 + h] * WSCALE;
    __half h0 = __float2half_rn(v0), h1 = __float2half_rn(v1);
    float l0 = v0 - __half2float(h0), l1 = v1 - __half2float(h1);
    uint32_t off = (uint32_t)h * SPB + (uint32_t)f * 2;
    *(uint32_t*)(g_w1s + off)       = ((uint32_t)*(uint16_t*)&h0) | ((uint32_t)*(uint16_t*)&h1 << 16);
    *(uint32_t*)(g_w1s + BUF + off) = pkh(l0, l1);
}

__global__ void prep_w2(const float* __restrict__ w2) {
    int t = blockIdx.x * 256 + threadIdx.x;
    if (t >= 8 * 128 * 64) return;
    int c = t >> 13, n = (t >> 6) & 127, f = (t & 63) * 2;
    int kg = c * 128 + n;
    float v0 = w2[f * 1024 + kg] * WSCALE, v1 = w2[(f + 1) * 1024 + kg] * WSCALE;
    __half h0 = __float2half_rn(v0), h1 = __float2half_rn(v1);
    float l0 = v0 - __half2float(h0), l1 = v1 - __half2float(h1);
    uint32_t off = (uint32_t)n * SPB + (uint32_t)f * 2;
    *(uint32_t*)(g_w2s[c] + off)       = ((uint32_t)*(uint16_t*)&h0) | ((uint32_t)*(uint16_t*)&h1 << 16);
    *(uint32_t*)(g_w2s[c] + BUF + off) = pkh(l0, l1);
}

// ---------------- main fused kernel: 256 threads, 4m x 2n warp grid ----------------
__global__ void __launch_bounds__(256, 1) fused_kernel(
    const float* __restrict__ x,  const int* __restrict__ ei,
    const float* __restrict__ ea, const float* __restrict__ esh,
    const float* __restrict__ b1, const float* __restrict__ b2)
{
    extern __shared__ unsigned char sm[];
    unsigned char* ABc = sm + AB_OFF;
    float* F   = (float*)(sm + FL_OFF);
    float* Sa0 = F + SA0;
    float* Sa1 = F + SA1;
    float* Sa3 = F + SA3;
    float* Sx1 = F + SX1;
    float* Ssh = F + SSH;
    int* Sdst  = (int*)(F + SDST);
    int* Ssrc  = (int*)(F + SSRC);
    float* b1s = F + SB1;
    float* b2s = F + SB2;
    float* Mg  = (float*)(sm + MG_OFF);     // [128][64] merge buffer (aliases W bufs)

    const int tid = threadIdx.x;
    const int wid = tid >> 5, lid = tid & 31;
    const int e0  = blockIdx.x * 128;
    const uint32_t sb = smem_u32(sm);

    // warp tile geometry: 4 m-groups (m32) x 2 n-halves (n64)
    const int m0 = (wid & 3) * 32;
    const int nq = wid >> 2;                       // 0 or 1
    const int rb = m0 + (lid >> 2);                // edge rows: rb, rb+8, rb+16, rb+24
    const int cb = (lid & 3) * 2;
    const uint32_t aoff = (uint32_t)(m0 + (lid & 15)) * SPB + (uint32_t)((lid >> 4) * 8) * 2;
    const uint32_t boff = (uint32_t)(nq * 64 + (lid & 7)) * SPB + (uint32_t)(lid >> 3) * 16;

    // ---- prefetch W1 -> WB0 (group 0), W2[0] -> WB1 (group 1) ----
    {
        const unsigned char* s1 = g_w1s;
        const unsigned char* s2 = g_w2s[0];
        #pragma unroll
        for (int i = 0; i < 17; i++) {
            uint32_t o = (uint32_t)(tid + i * 256) * 16;
            cp16(sb + WB0_OFF + o, s1 + o);
        }
        CP_COMMIT();
        #pragma unroll
        for (int i = 0; i < 17; i++) {
            uint32_t o = (uint32_t)(tid + i * 256) * 16;
            cp16(sb + WB1_OFF + o, s2 + o);
        }
        CP_COMMIT();
    }

    // ---- stage biases ----
    if (tid < 128) b1s[tid] = b1[tid];
    #pragma unroll
    for (int i = 0; i < 4; i++) b2s[tid + i * 256] = b2[tid + i * 256];

    // ---- phase 1: indices + sh ----
    if (tid < 128) {
        int eg = e0 + tid;
        Ssrc[tid] = ei[eg];
        Sdst[tid] = ei[E_TOTAL + eg];
        float4 s = *(const float4*)(esh + (size_t)eg * 4);
        Ssh[tid*4+0] = s.x; Ssh[tid*4+1] = s.y; Ssh[tid*4+2] = s.z; Ssh[tid*4+3] = s.w;
    }
    __syncthreads();

    // ---- phase 2: gather x[src] + TP precompute ----
    {
        int e = tid & 127, part = tid >> 7;
        int src = Ssrc[e];
        const float4* xr = (const float4*)(x + (size_t)src * 64);
        if (part == 0) {
            float sh0 = Ssh[e*4];
            #pragma unroll
            for (int q = 0; q < 4; q++) {
                float4 xv = xr[q];
                int u = q * 4;
                Sa1[e*16+u+0] = xv.x;  Sa0[e*16+u+0] = xv.x * sh0;
                Sa1[e*16+u+1] = xv.y;  Sa0[e*16+u+1] = xv.y * sh0;
                Sa1[e*16+u+2] = xv.z;  Sa0[e*16+u+2] = xv.z * sh0;
                Sa1[e*16+u+3] = xv.w;  Sa0[e*16+u+3] = xv.w * sh0;
            }
        } else {
            float s1x = Ssh[e*4+1], s1y = Ssh[e*4+2], s1z = Ssh[e*4+3];
            float x1l[48];
            #pragma unroll
            for (int q = 0; q < 12; q++) {
                float4 xv = xr[4 + q];
                x1l[q*4+0]=xv.x; x1l[q*4+1]=xv.y; x1l[q*4+2]=xv.z; x1l[q*4+3]=xv.w;
                *(float4*)(Sx1 + e*48 + q*4) = xv;
            }
            #pragma unroll
            for (int u = 0; u < 16; u++) {
                float d = x1l[u*3]*s1x + x1l[u*3+1]*s1y + x1l[u*3+2]*s1z;
                Sa3[e*16+u] = d * 0.57735026918962576f;
            }
        }
    }

    // ---- EA tile -> fp16 into A buffer (half row per thread) ----
    {
        int r = tid >> 1, hf = tid & 1;
        const float4* rowp = (const float4*)(ea + (size_t)(e0 + r) * 128 + hf * 64);
        uint32_t* dst = (uint32_t*)(ABc + (uint32_t)r * SPB + (uint32_t)(hf * 64) * 2);
        #pragma unroll
        for (int j = 0; j < 16; j++) {
            float4 v = rowp[j];
            dst[j*2]     = pkh(v.x, v.y);
            dst[j*2 + 1] = pkh(v.z, v.w);
        }
    }

    // ---- GEMM1: H = relu(acc/S + b1) ----
    CP_WAIT(1);     // W1 resident (W2[0] may still be in flight)
    __syncthreads();

    float acc[2][8][4];
    #pragma unroll
    for (int mt = 0; mt < 2; mt++)
        #pragma unroll
        for (int nt = 0; nt < 8; nt++)
            #pragma unroll
            for (int q = 0; q < 4; q++) acc[mt][nt][q] = 0.0f;

    gemm2p(acc, sb + AB_OFF, sb + WB0_OFF, aoff, boff);
    __syncthreads();   // all warps done reading EA

    // writeback H as fp16 (cols nq*64 + nt*8 + cb)
    #pragma unroll
    for (int mt = 0; mt < 2; mt++) {
        int r0 = rb + mt * 16, r1 = r0 + 8;
        #pragma unroll
        for (int nt = 0; nt < 8; nt++) {
            int c = nq * 64 + nt * 8 + cb;
            float bb0 = b1s[c], bb1 = b1s[c + 1];
            float h0 = fmaxf(fmaf(acc[mt][nt][0], INV_S, bb0), 0.0f);
            float h1 = fmaxf(fmaf(acc[mt][nt][1], INV_S, bb1), 0.0f);
            float h2 = fmaxf(fmaf(acc[mt][nt][2], INV_S, bb0), 0.0f);
            float h3 = fmaxf(fmaf(acc[mt][nt][3], INV_S, bb1), 0.0f);
            *(uint32_t*)(ABc + (uint32_t)r0 * SPB + (uint32_t)c * 2) = pkh(h0, h1);
            *(uint32_t*)(ABc + (uint32_t)r1 * SPB + (uint32_t)c * 2) = pkh(h2, h3);
        }
    }

    // ---- GEMM2 chunks + TP consumption ----
    float s0[4][4], t1[4][4], o1[4][4][3];
    #pragma unroll
    for (int er = 0; er < 4; er++)
        #pragma unroll
        for (int vi = 0; vi < 4; vi++) {
            s0[er][vi] = 0.0f; t1[er][vi] = 0.0f;
            o1[er][vi][0] = 0.0f; o1[er][vi][1] = 0.0f; o1[er][vi][2] = 0.0f;
        }

    #pragma unroll 1
    for (int ch = 0; ch < 8; ch++) {
        // prefetch next chunk into the buffer whose reads finished last iter
        if (ch < 7) {
            const unsigned char* s2 = g_w2s[ch + 1];
            uint32_t dsto = (ch & 1) ? WB1_OFF : WB0_OFF;
            #pragma unroll
            for (int i = 0; i < 17; i++) {
                uint32_t o = (uint32_t)(tid + i * 256) * 16;
                cp16(sb + dsto + o, s2 + o);
            }
            CP_COMMIT();
            CP_WAIT(1);     // chunk ch resident, ch+1 in flight
        } else {
            CP_WAIT(0);
        }
        __syncthreads();    // data visible + H writes (iter0) ordered

        #pragma unroll
        for (int mt = 0; mt < 2; mt++)
            #pragma unroll
            for (int nt = 0; nt < 8; nt++)
                #pragma unroll
                for (int q = 0; q < 4; q++) acc[mt][nt][q] = 0.0f;

        uint32_t wbase = (ch & 1) ? (sb + WB0_OFF) : (sb + WB1_OFF);
        gemm2p(acc, sb + AB_OFF, wbase, aoff, boff);

        // epilogue: wv = acc/S + b2 ; u = (ch&1)*8 + nq*4 + (nt>>1) ; v = (nt&1)*8 + cb + d
        const int p  = ch >> 1;
        const int ub = (ch & 1) * 8 + nq * 4;
        const float* b2c = b2s + ch * 128 + nq * 64;

        if (p == 2) {
            #pragma unroll
            for (int mt = 0; mt < 2; mt++) {
                int r0 = rb + mt * 16;
                #pragma unroll
                for (int nt = 0; nt < 8; nt++) {
                    int u = ub + (nt >> 1);
                    float xa0 = Sx1[r0*48 + u*3 + 0], xb0 = Sx1[r0*48 + u*3 + 1], xc0 = Sx1[r0*48 + u*3 + 2];
                    float xa1 = Sx1[(r0+8)*48 + u*3 + 0], xb1 = Sx1[(r0+8)*48 + u*3 + 1], xc1 = Sx1[(r0+8)*48 + u*3 + 2];
                    #pragma unroll
                    for (int d = 0; d < 2; d++) {
                        float bb = b2c[nt*8 + cb + d];
                        int vi = (nt & 1) * 2 + d;
                        float w0 = fmaf(acc[mt][nt][d],     INV_S, bb);
                        float w1 = fmaf(acc[mt][nt][2 + d], INV_S, bb);
                        int ea0 = mt * 2, ea1 = mt * 2 + 1;
                        o1[ea0][vi][0] = fmaf(xa0, w0, o1[ea0][vi][0]);
                        o1[ea0][vi][1] = fmaf(xb0, w0, o1[ea0][vi][1]);
                        o1[ea0][vi][2] = fmaf(xc0, w0, o1[ea0][vi][2]);
                        o1[ea1][vi][0] = fmaf(xa1, w1, o1[ea1][vi][0]);
                        o1[ea1][vi][1] = fmaf(xb1, w1, o1[ea1][vi][1]);
                        o1[ea1][vi][2] = fmaf(xc1, w1, o1[ea1][vi][2]);
                    }
                }
            }
        } else {
            const float* A = (p == 0) ? Sa0 : (p == 1) ? Sa1 : Sa3;
            float av[4][4];
            #pragma unroll
            for (int er = 0; er < 4; er++) {
                int r = rb + (er >> 1) * 16 + (er & 1) * 8;
                #pragma unroll
                for (int u = 0; u < 4; u++) av[er][u] = A[r*16 + ub + u];
            }
            if (p == 1) {
                #pragma unroll
                for (int mt = 0; mt < 2; mt++)
                    #pragma unroll
                    for (int nt = 0; nt < 8; nt++) {
                        int u = nt >> 1;
                        #pragma unroll
                        for (int d = 0; d < 2; d++) {
                            float bb = b2c[nt*8 + cb + d];
                            int vi = (nt & 1) * 2 + d;
                            t1[mt*2][vi]   = fmaf(av[mt*2][u],   fmaf(acc[mt][nt][d],     INV_S, bb), t1[mt*2][vi]);
                            t1[mt*2+1][vi] = fmaf(av[mt*2+1][u], fmaf(acc[mt][nt][2 + d], INV_S, bb), t1[mt*2+1][vi]);
                        }
                    }
            } else {
                #pragma unroll
                for (int mt = 0; mt < 2; mt++)
                    #pragma unroll
                    for (int nt = 0; nt < 8; nt++) {
                        int u = nt >> 1;
                        #pragma unroll
                        for (int d = 0; d < 2; d++) {
                            float bb = b2c[nt*8 + cb + d];
                            int vi = (nt & 1) * 2 + d;
                            s0[mt*2][vi]   = fmaf(av[mt*2][u],   fmaf(acc[mt][nt][d],     INV_S, bb), s0[mt*2][vi]);
                            s0[mt*2+1][vi] = fmaf(av[mt*2+1][u], fmaf(acc[mt][nt][2 + d], INV_S, bb), s0[mt*2+1][vi]);
                        }
                    }
            }
        }
        __syncthreads();   // weight-buffer reads done before next iter's prefetch overwrites
    }

    // ---- merge the two n-halves in SMEM, then single scatter-add per output ----
    {
        if (nq == 0) {
            #pragma unroll
            for (int er = 0; er < 4; er++) {
                int e = rb + (er >> 1) * 16 + (er & 1) * 8;
                float sh0 = Ssh[e*4+0];
                float s1x = Ssh[e*4+1], s1y = Ssh[e*4+2], s1z = Ssh[e*4+3];
                float* mrow = Mg + e * 64;
                #pragma unroll
                for (int vi = 0; vi < 4; vi++) {
                    int v = cb + (vi >> 1) * 8 + (vi & 1);
                    mrow[v]            = s0[er][vi];
                    mrow[16 + v*3 + 0] = t1[er][vi]*s1x + sh0*o1[er][vi][0];
                    mrow[16 + v*3 + 1] = t1[er][vi]*s1y + sh0*o1[er][vi][1];
                    mrow[16 + v*3 + 2] = t1[er][vi]*s1z + sh0*o1[er][vi][2];
                }
            }
        }
        __syncthreads();
        if (nq == 1) {
            const float alpha = 0.17677669529663689f;  // 1/sqrt(2*16)
            #pragma unroll
            for (int er = 0; er < 4; er++) {
                int e = rb + (er >> 1) * 16 + (er & 1) * 8;
                int dst = Sdst[e];
                float sh0 = Ssh[e*4+0];
                float s1x = Ssh[e*4+1], s1y = Ssh[e*4+2], s1z = Ssh[e*4+3];
                float* mrow = Mg + e * 64;
                float* base = g_acc + (size_t)dst * 64;
                #pragma unroll
                for (int vi = 0; vi < 4; vi++) {
                    int v = cb + (vi >> 1) * 8 + (vi & 1);
                    atomicAdd(base + v, alpha * (s0[er][vi] + mrow[v]));
                    atomicAdd(base + 16 + v*3 + 0,
                        alpha * (t1[er][vi]*s1x + sh0*o1[er][vi][0] + mrow[16 + v*3 + 0]));
                    atomicAdd(base + 16 + v*3 + 1,
                        alpha * (t1[er][vi]*s1y + sh0*o1[er][vi][1] + mrow[16 + v*3 + 1]));
                    atomicAdd(base + 16 + v*3 + 2,
                        alpha * (t1[er][vi]*s1z + sh0*o1[er][vi][2] + mrow[16 + v*3 + 2]));
                }
                if ((lid & 3) == 0) atomicAdd(&g_cnt[dst], 1.0f);
            }
        }
    }
}

__global__ void finalize_kernel(const float* __restrict__ x, float* __restrict__ out) {
    int i = blockIdx.x * blockDim.x + threadIdx.x;
    if (i < NNODES * 64) {
        int node = i >> 6;
        out[i] = g_acc[i] / fmaxf(g_cnt[node], 1.0f) + x[i];
    }
}

extern "C" void kernel_launch(void* const* d_in, const int* in_sizes, int n_in,
                              void* d_out, int out_size)
{
    const float* x   = (const float*)d_in[0];
    const int*   ei  = (const int*)  d_in[1];
    const float* ea  = (const float*)d_in[2];
    const float* esh = (const float*)d_in[3];
    const float* w1  = (const float*)d_in[4];
    const float* b1  = (const float*)d_in[5];
    const float* w2  = (const float*)d_in[6];
    const float* b2  = (const float*)d_in[7];
    float* out = (float*)d_out;

    cudaFuncSetAttribute(fused_kernel,
                         cudaFuncAttributeMaxDynamicSharedMemorySize, SMEM_BYTES);

    int ztot = NNODES * 64 + NNODES;
    zero_kernel<<<(ztot + 255) / 256, 256>>>();
    prep_w1<<<(128 * 64 + 255) / 256, 256>>>(w1);
    prep_w2<<<(8 * 128 * 64 + 255) / 256, 256>>>(w2);
    fused_kernel<<<NBLK, 256, SMEM_BYTES>>>(x, ei, ea, esh, b1, b2);
    finalize_kernel<<<(NNODES * 64 + 255) / 256, 256>>>(x, out);
}

// round 9
// speedup vs baseline: 1.9777x; 1.3429x over previous
#include <cuda_runtime.h>
#include <cuda_fp16.h>
#include <cstdint>

#define E_TOTAL 160000
#define NNODES  10000
#define NBLK    1250

#define SP   136                 // padded row stride (fp16 elems)
#define SPB  272                 // row stride bytes
#define BUF  (128 * SPB)         // 34816 B: one 128x136 fp16 buffer

// ---------------- SMEM layout (bytes) ----------------
#define AB_OFF  0                // A operand fp16 (EA tile, later H tile)
#define WB0_OFF (1 * BUF)        // W1 hi      (later: merge buffer)
#define WB1_OFF (2 * BUF)        // W1 lo
#define WB2_OFF (3 * BUF)        // W2 ping
#define WB3_OFF (4 * BUF)        // W2 pong
#define FL_OFF  (5 * BUF)        // 174080: float region
#define SA0  0                   // x0*sh0      [128][16]
#define SA1  2048                // x0          [128][16]
#define SA3  4096                // dot/sqrt3   [128][16]
#define SX1  6144                // x1          [128][48]
#define SSH  12288               // sh          [128][4]
#define SDST 12800               // int [128]
#define SSRC 12928               // int [128]
#define SB1  13056               // b1 [128]
#define SB2  13184               // b2 [1024]
#define NFL  14208
#define SMEM_BYTES (FL_OFF + NFL * 4)   // 230912
#define MG_OFF  WB0_OFF          // merge buffer aliases W1 area (dead after GEMM1)

#define WSCALE 256.0f
#define INV_S  (1.0f / 256.0f)

__device__ float g_acc[NNODES * 64];
__device__ float g_cnt[NNODES];
__device__ __align__(16) unsigned char g_w1s[2 * BUF];    // W1T hi + lo, scaled
__device__ __align__(16) unsigned char g_w2s[8][BUF];     // per N-chunk W2T hi only, scaled

// ---------------- helpers ----------------
__device__ __forceinline__ uint32_t smem_u32(const void* p) {
    uint32_t a;
    asm("{ .reg .u64 t; cvta.to.shared.u64 t, %1; cvt.u32.u64 %0, t; }" : "=r"(a) : "l"(p));
    return a;
}
__device__ __forceinline__ void ldsm_x4(uint32_t* r, uint32_t addr) {
    asm volatile("ldmatrix.sync.aligned.m8n8.x4.shared.b16 {%0,%1,%2,%3}, [%4];"
        : "=r"(r[0]), "=r"(r[1]), "=r"(r[2]), "=r"(r[3]) : "r"(addr));
}
__device__ __forceinline__ void mma16816(float* c, const uint32_t* a, const uint32_t* b) {
    asm volatile("mma.sync.aligned.m16n8k16.row.col.f32.f16.f16.f32 "
        "{%0,%1,%2,%3}, {%4,%5,%6,%7}, {%8,%9}, {%0,%1,%2,%3};"
        : "+f"(c[0]), "+f"(c[1]), "+f"(c[2]), "+f"(c[3])
        : "r"(a[0]), "r"(a[1]), "r"(a[2]), "r"(a[3]), "r"(b[0]), "r"(b[1]));
}
__device__ __forceinline__ uint32_t pkh(float a, float b) {
    __half2 h = __floats2half2_rn(a, b);
    return *(uint32_t*)&h;
}
__device__ __forceinline__ void cp16(uint32_t dst, const void* src) {
    asm volatile("cp.async.cg.shared.global [%0], [%1], 16;" :: "r"(dst), "l"(src));
}
#define CP_COMMIT() asm volatile("cp.async.commit_group;" ::: "memory")
#define CP_WAIT(n)  asm volatile("cp.async.wait_group %0;" :: "n"(n) : "memory")

// warp tile m32 x n64 x k128, single pass against one B buffer.
__device__ __forceinline__ void gemm_1p(float acc[2][8][4],
                                        uint32_t a_base, uint32_t w_base,
                                        uint32_t aoff, uint32_t boff) {
    #pragma unroll
    for (int kp = 0; kp < 4; kp++) {        // k32 per iteration
        uint32_t Am[2][8];                  // [0..3]=k16lo frag, [4..7]=k16hi frag
        ldsm_x4(Am[0],     a_base + aoff + kp * 64);
        ldsm_x4(Am[0] + 4, a_base + aoff + kp * 64 + 32);
        ldsm_x4(Am[1],     a_base + aoff + 16 * SPB + kp * 64);
        ldsm_x4(Am[1] + 4, a_base + aoff + 16 * SPB + kp * 64 + 32);
        #pragma unroll
        for (int nt = 0; nt < 8; nt++) {
            uint32_t Bf[4];
            uint32_t wb = (uint32_t)nt * (8 * SPB) + boff + kp * 64;
            ldsm_x4(Bf, w_base + wb);
            #pragma unroll
            for (int mt = 0; mt < 2; mt++) {
                mma16816(acc[mt][nt], Am[mt],     Bf);
                mma16816(acc[mt][nt], Am[mt] + 4, Bf + 2);
            }
        }
    }
}

// ---------------- small kernels ----------------
__global__ void zero_kernel() {
    int i = blockIdx.x * blockDim.x + threadIdx.x;
    if (i < NNODES * 64) g_acc[i] = 0.0f;
    else if (i < NNODES * 64 + NNODES) g_cnt[i - NNODES * 64] = 0.0f;
}

__global__ void prep_w1(const float* __restrict__ w1) {
    int t = blockIdx.x * 256 + threadIdx.x;
    if (t >= 128 * 64) return;
    int h = t >> 6, f = (t & 63) * 2;
    float v0 = w1[f * 128 + h] * WSCALE, v1 = w1[(f + 1) * 128 + h] * WSCALE;
    __half h0 = __float2half_rn(v0), h1 = __float2half_rn(v1);
    float l0 = v0 - __half2float(h0), l1 = v1 - __half2float(h1);
    uint32_t off = (uint32_t)h * SPB + (uint32_t)f * 2;
    *(uint32_t*)(g_w1s + off)       = ((uint32_t)*(uint16_t*)&h0) | ((uint32_t)*(uint16_t*)&h1 << 16);
    *(uint32_t*)(g_w1s + BUF + off) = pkh(l0, l1);
}

__global__ void prep_w2(const float* __restrict__ w2) {
    int t = blockIdx.x * 256 + threadIdx.x;
    if (t >= 8 * 128 * 64) return;
    int c = t >> 13, n = (t >> 6) & 127, f = (t & 63) * 2;
    int kg = c * 128 + n;
    float v0 = w2[f * 1024 + kg] * WSCALE, v1 = w2[(f + 1) * 1024 + kg] * WSCALE;
    uint32_t off = (uint32_t)n * SPB + (uint32_t)f * 2;
    *(uint32_t*)(g_w2s[c] + off) = pkh(v0, v1);   // hi only
}

// ---------------- main fused kernel: 256 threads, 4m x 2n warp grid ----------------
__global__ void __launch_bounds__(256, 1) fused_kernel(
    const float* __restrict__ x,  const int* __restrict__ ei,
    const float* __restrict__ ea, const float* __restrict__ esh,
    const float* __restrict__ b1, const float* __restrict__ b2)
{
    extern __shared__ unsigned char sm[];
    unsigned char* ABc = sm + AB_OFF;
    float* F   = (float*)(sm + FL_OFF);
    float* Sa0 = F + SA0;
    float* Sa1 = F + SA1;
    float* Sa3 = F + SA3;
    float* Sx1 = F + SX1;
    float* Ssh = F + SSH;
    int* Sdst  = (int*)(F + SDST);
    int* Ssrc  = (int*)(F + SSRC);
    float* b1s = F + SB1;
    float* b2s = F + SB2;
    float* Mg  = (float*)(sm + MG_OFF);     // [128][64] merge buffer (aliases W1 bufs)

    const int tid = threadIdx.x;
    const int wid = tid >> 5, lid = tid & 31;
    const int e0  = blockIdx.x * 128;
    const uint32_t sb = smem_u32(sm);

    // warp tile geometry: 4 m-groups (m32) x 2 n-halves (n64)
    const int m0 = (wid & 3) * 32;
    const int nq = wid >> 2;                       // 0 or 1
    const int rb = m0 + (lid >> 2);                // edge rows: rb, rb+8, rb+16, rb+24
    const int cb = (lid & 3) * 2;
    const uint32_t aoff = (uint32_t)(m0 + (lid & 15)) * SPB + (uint32_t)((lid >> 4) * 8) * 2;
    const uint32_t boff = (uint32_t)(nq * 64 + (lid & 7)) * SPB + (uint32_t)(lid >> 3) * 16;

    // ---- prefetch: G0 = W1(hi+lo), G1 = W2[0], G2 = W2[1] ----
    {
        #pragma unroll
        for (int i = 0; i < 17; i++) {
            uint32_t o = (uint32_t)(tid + i * 256) * 16;     // covers 2*BUF
            cp16(sb + WB0_OFF + o, g_w1s + o);
        }
        CP_COMMIT();
        #pragma unroll
        for (int i = 0; i < 9; i++) {
            uint32_t o = (uint32_t)(tid + i * 256) * 16;
            if (o < BUF) cp16(sb + WB2_OFF + o, g_w2s[0] + o);
        }
        CP_COMMIT();
        #pragma unroll
        for (int i = 0; i < 9; i++) {
            uint32_t o = (uint32_t)(tid + i * 256) * 16;
            if (o < BUF) cp16(sb + WB3_OFF + o, g_w2s[1] + o);
        }
        CP_COMMIT();
    }

    // ---- stage biases ----
    if (tid < 128) b1s[tid] = b1[tid];
    #pragma unroll
    for (int i = 0; i < 4; i++) b2s[tid + i * 256] = b2[tid + i * 256];

    // ---- phase 1: indices + sh ----
    if (tid < 128) {
        int eg = e0 + tid;
        Ssrc[tid] = ei[eg];
        Sdst[tid] = ei[E_TOTAL + eg];
        float4 s = *(const float4*)(esh + (size_t)eg * 4);
        Ssh[tid*4+0] = s.x; Ssh[tid*4+1] = s.y; Ssh[tid*4+2] = s.z; Ssh[tid*4+3] = s.w;
    }
    __syncthreads();

    // ---- phase 2: gather x[src] + TP precompute ----
    {
        int e = tid & 127, part = tid >> 7;
        int src = Ssrc[e];
        const float4* xr = (const float4*)(x + (size_t)src * 64);
        if (part == 0) {
            float sh0 = Ssh[e*4];
            #pragma unroll
            for (int q = 0; q < 4; q++) {
                float4 xv = xr[q];
                int u = q * 4;
                Sa1[e*16+u+0] = xv.x;  Sa0[e*16+u+0] = xv.x * sh0;
                Sa1[e*16+u+1] = xv.y;  Sa0[e*16+u+1] = xv.y * sh0;
                Sa1[e*16+u+2] = xv.z;  Sa0[e*16+u+2] = xv.z * sh0;
                Sa1[e*16+u+3] = xv.w;  Sa0[e*16+u+3] = xv.w * sh0;
            }
        } else {
            float s1x = Ssh[e*4+1], s1y = Ssh[e*4+2], s1z = Ssh[e*4+3];
            float x1l[48];
            #pragma unroll
            for (int q = 0; q < 12; q++) {
                float4 xv = xr[4 + q];
                x1l[q*4+0]=xv.x; x1l[q*4+1]=xv.y; x1l[q*4+2]=xv.z; x1l[q*4+3]=xv.w;
                *(float4*)(Sx1 + e*48 + q*4) = xv;
            }
            #pragma unroll
            for (int u = 0; u < 16; u++) {
                float d = x1l[u*3]*s1x + x1l[u*3+1]*s1y + x1l[u*3+2]*s1z;
                Sa3[e*16+u] = d * 0.57735026918962576f;
            }
        }
    }

    // ---- EA tile -> fp16 into A buffer (half row per thread) ----
    {
        int r = tid >> 1, hf = tid & 1;
        const float4* rowp = (const float4*)(ea + (size_t)(e0 + r) * 128 + hf * 64);
        uint32_t* dst = (uint32_t*)(ABc + (uint32_t)r * SPB + (uint32_t)(hf * 64) * 2);
        #pragma unroll
        for (int j = 0; j < 16; j++) {
            float4 v = rowp[j];
            dst[j*2]     = pkh(v.x, v.y);
            dst[j*2 + 1] = pkh(v.z, v.w);
        }
    }

    // ---- GEMM1: H = relu(acc/S + b1), 2 passes (W1 hi, W1 lo) ----
    CP_WAIT(2);     // W1 resident (W2[0], W2[1] may still be in flight)
    __syncthreads();

    float acc[2][8][4];
    #pragma unroll
    for (int mt = 0; mt < 2; mt++)
        #pragma unroll
        for (int nt = 0; nt < 8; nt++)
            #pragma unroll
            for (int q = 0; q < 4; q++) acc[mt][nt][q] = 0.0f;

    gemm_1p(acc, sb + AB_OFF, sb + WB0_OFF, aoff, boff);
    gemm_1p(acc, sb + AB_OFF, sb + WB1_OFF, aoff, boff);
    __syncthreads();   // all warps done reading EA

    // writeback H as fp16 (cols nq*64 + nt*8 + cb)
    #pragma unroll
    for (int mt = 0; mt < 2; mt++) {
        int r0 = rb + mt * 16, r1 = r0 + 8;
        #pragma unroll
        for (int nt = 0; nt < 8; nt++) {
            int c = nq * 64 + nt * 8 + cb;
            float bb0 = b1s[c], bb1 = b1s[c + 1];
            float h0 = fmaxf(fmaf(acc[mt][nt][0], INV_S, bb0), 0.0f);
            float h1 = fmaxf(fmaf(acc[mt][nt][1], INV_S, bb1), 0.0f);
            float h2 = fmaxf(fmaf(acc[mt][nt][2], INV_S, bb0), 0.0f);
            float h3 = fmaxf(fmaf(acc[mt][nt][3], INV_S, bb1), 0.0f);
            *(uint32_t*)(ABc + (uint32_t)r0 * SPB + (uint32_t)c * 2) = pkh(h0, h1);
            *(uint32_t*)(ABc + (uint32_t)r1 * SPB + (uint32_t)c * 2) = pkh(h2, h3);
        }
    }

    // ---- GEMM2 chunks (single-pass) + TP consumption ----
    float s0[4][4], t1[4][4], o1[4][4][3];
    #pragma unroll
    for (int er = 0; er < 4; er++)
        #pragma unroll
        for (int vi = 0; vi < 4; vi++) {
            s0[er][vi] = 0.0f; t1[er][vi] = 0.0f;
            o1[er][vi][0] = 0.0f; o1[er][vi][1] = 0.0f; o1[er][vi][2] = 0.0f;
        }

    #pragma unroll 1
    for (int ch = 0; ch < 8; ch++) {
        CP_WAIT(1);         // W2[ch] resident (at most W2[ch+1] pending)
        __syncthreads();    // cp.async data visible to all; H writes ordered (iter 0)

        #pragma unroll
        for (int mt = 0; mt < 2; mt++)
            #pragma unroll
            for (int nt = 0; nt < 8; nt++)
                #pragma unroll
                for (int q = 0; q < 4; q++) acc[mt][nt][q] = 0.0f;

        uint32_t wbase = (ch & 1) ? (sb + WB3_OFF) : (sb + WB2_OFF);
        gemm_1p(acc, sb + AB_OFF, wbase, aoff, boff);

        // epilogue: wv = acc/S + b2 ; u = (ch&1)*8 + nq*4 + (nt>>1) ; v = (nt&1)*8 + cb + d
        const int p  = ch >> 1;
        const int ub = (ch & 1) * 8 + nq * 4;
        const float* b2c = b2s + ch * 128 + nq * 64;

        if (p == 2) {
            #pragma unroll
            for (int mt = 0; mt < 2; mt++) {
                int r0 = rb + mt * 16;
                #pragma unroll
                for (int nt = 0; nt < 8; nt++) {
                    int u = ub + (nt >> 1);
                    float xa0 = Sx1[r0*48 + u*3 + 0], xb0 = Sx1[r0*48 + u*3 + 1], xc0 = Sx1[r0*48 + u*3 + 2];
                    float xa1 = Sx1[(r0+8)*48 + u*3 + 0], xb1 = Sx1[(r0+8)*48 + u*3 + 1], xc1 = Sx1[(r0+8)*48 + u*3 + 2];
                    #pragma unroll
                    for (int d = 0; d < 2; d++) {
                        float bb = b2c[nt*8 + cb + d];
                        int vi = (nt & 1) * 2 + d;
                        float w0 = fmaf(acc[mt][nt][d],     INV_S, bb);
                        float w1 = fmaf(acc[mt][nt][2 + d], INV_S, bb);
                        int ea0 = mt * 2, ea1 = mt * 2 + 1;
                        o1[ea0][vi][0] = fmaf(xa0, w0, o1[ea0][vi][0]);
                        o1[ea0][vi][1] = fmaf(xb0, w0, o1[ea0][vi][1]);
                        o1[ea0][vi][2] = fmaf(xc0, w0, o1[ea0][vi][2]);
                        o1[ea1][vi][0] = fmaf(xa1, w1, o1[ea1][vi][0]);
                        o1[ea1][vi][1] = fmaf(xb1, w1, o1[ea1][vi][1]);
                        o1[ea1][vi][2] = fmaf(xc1, w1, o1[ea1][vi][2]);
                    }
                }
            }
        } else {
            const float* A = (p == 0) ? Sa0 : (p == 1) ? Sa1 : Sa3;
            float av[4][4];
            #pragma unroll
            for (int er = 0; er < 4; er++) {
                int r = rb + (er >> 1) * 16 + (er & 1) * 8;
                #pragma unroll
                for (int u = 0; u < 4; u++) av[er][u] = A[r*16 + ub + u];
            }
            if (p == 1) {
                #pragma unroll
                for (int mt = 0; mt < 2; mt++)
                    #pragma unroll
                    for (int nt = 0; nt < 8; nt++) {
                        int u = nt >> 1;
                        #pragma unroll
                        for (int d = 0; d < 2; d++) {
                            float bb = b2c[nt*8 + cb + d];
                            int vi = (nt & 1) * 2 + d;
                            t1[mt*2][vi]   = fmaf(av[mt*2][u],   fmaf(acc[mt][nt][d],     INV_S, bb), t1[mt*2][vi]);
                            t1[mt*2+1][vi] = fmaf(av[mt*2+1][u], fmaf(acc[mt][nt][2 + d], INV_S, bb), t1[mt*2+1][vi]);
                        }
                    }
            } else {
                #pragma unroll
                for (int mt = 0; mt < 2; mt++)
                    #pragma unroll
                    for (int nt = 0; nt < 8; nt++) {
                        int u = nt >> 1;
                        #pragma unroll
                        for (int d = 0; d < 2; d++) {
                            float bb = b2c[nt*8 + cb + d];
                            int vi = (nt & 1) * 2 + d;
                            s0[mt*2][vi]   = fmaf(av[mt*2][u],   fmaf(acc[mt][nt][d],     INV_S, bb), s0[mt*2][vi]);
                            s0[mt*2+1][vi] = fmaf(av[mt*2+1][u], fmaf(acc[mt][nt][2 + d], INV_S, bb), s0[mt*2+1][vi]);
                        }
                    }
            }
        }
        __syncthreads();   // all reads of buffer (ch&1) complete before refill

        // prefetch W2[ch+2] into the buffer just freed
        if (ch + 2 <= 7) {
            const unsigned char* s2 = g_w2s[ch + 2];
            uint32_t dsto = (ch & 1) ? WB3_OFF : WB2_OFF;
            #pragma unroll
            for (int i = 0; i < 9; i++) {
                uint32_t o = (uint32_t)(tid + i * 256) * 16;
                if (o < BUF) cp16(sb + dsto + o, s2 + o);
            }
            CP_COMMIT();
        }
    }

    // ---- merge the two n-halves in SMEM, then single scatter-add per output ----
    {
        if (nq == 0) {
            #pragma unroll
            for (int er = 0; er < 4; er++) {
                int e = rb + (er >> 1) * 16 + (er & 1) * 8;
                float sh0 = Ssh[e*4+0];
                float s1x = Ssh[e*4+1], s1y = Ssh[e*4+2], s1z = Ssh[e*4+3];
                float* mrow = Mg + e * 64;
                #pragma unroll
                for (int vi = 0; vi < 4; vi++) {
                    int v = cb + (vi >> 1) * 8 + (vi & 1);
                    mrow[v]            = s0[er][vi];
                    mrow[16 + v*3 + 0] = t1[er][vi]*s1x + sh0*o1[er][vi][0];
                    mrow[16 + v*3 + 1] = t1[er][vi]*s1y + sh0*o1[er][vi][1];
                    mrow[16 + v*3 + 2] = t1[er][vi]*s1z + sh0*o1[er][vi][2];
                }
            }
        }
        __syncthreads();
        if (nq == 1) {
            const float alpha = 0.17677669529663689f;  // 1/sqrt(2*16)
            #pragma unroll
            for (int er = 0; er < 4; er++) {
                int e = rb + (er >> 1) * 16 + (er & 1) * 8;
                int dst = Sdst[e];
                float sh0 = Ssh[e*4+0];
                float s1x = Ssh[e*4+1], s1y = Ssh[e*4+2], s1z = Ssh[e*4+3];
                float* mrow = Mg + e * 64;
                float* base = g_acc + (size_t)dst * 64;
                #pragma unroll
                for (int vi = 0; vi < 4; vi++) {
                    int v = cb + (vi >> 1) * 8 + (vi & 1);
                    atomicAdd(base + v, alpha * (s0[er][vi] + mrow[v]));
                    atomicAdd(base + 16 + v*3 + 0,
                        alpha * (t1[er][vi]*s1x + sh0*o1[er][vi][0] + mrow[16 + v*3 + 0]));
                    atomicAdd(base + 16 + v*3 + 1,
                        alpha * (t1[er][vi]*s1y + sh0*o1[er][vi][1] + mrow[16 + v*3 + 1]));
                    atomicAdd(base + 16 + v*3 + 2,
                        alpha * (t1[er][vi]*s1z + sh0*o1[er][vi][2] + mrow[16 + v*3 + 2]));
                }
                if ((lid & 3) == 0) atomicAdd(&g_cnt[dst], 1.0f);
            }
        }
    }
}

__global__ void finalize_kernel(const float* __restrict__ x, float* __restrict__ out) {
    int i = blockIdx.x * blockDim.x + threadIdx.x;
    if (i < NNODES * 64) {
        int node = i >> 6;
        out[i] = g_acc[i] / fmaxf(g_cnt[node], 1.0f) + x[i];
    }
}

extern "C" void kernel_launch(void* const* d_in, const int* in_sizes, int n_in,
                              void* d_out, int out_size)
{
    const float* x   = (const float*)d_in[0];
    const int*   ei  = (const int*)  d_in[1];
    const float* ea  = (const float*)d_in[2];
    const float* esh = (const float*)d_in[3];
    const float* w1  = (const float*)d_in[4];
    const float* b1  = (const float*)d_in[5];
    const float* w2  = (const float*)d_in[6];
    const float* b2  = (const float*)d_in[7];
    float* out = (float*)d_out;

    cudaFuncSetAttribute(fused_kernel,
                         cudaFuncAttributeMaxDynamicSharedMemorySize, SMEM_BYTES);

    int ztot = NNODES * 64 + NNODES;
    zero_kernel<<<(ztot + 255) / 256, 256>>>();
    prep_w1<<<(128 * 64 + 255) / 256, 256>>>(w1);
    prep_w2<<<(8 * 128 * 64 + 255) / 256, 256>>>(w2);
    fused_kernel<<<NBLK, 256, SMEM_BYTES>>>(x, ei, ea, esh, b1, b2);
    finalize_kernel<<<(NNODES * 64 + 255) / 256, 256>>>(x, out);
}

// round 10
// speedup vs baseline: 2.0831x; 1.0533x over previous
#include <cuda_runtime.h>
#include <cuda_fp16.h>
#include <cstdint>

#define E_TOTAL 160000
#define NNODES  10000
#define NBLK    2500
#define TEDGE   64

#define SP   136                 // padded row stride (fp16 elems)
#define SPB  272                 // row stride bytes
#define ABUF (64 * SPB)          // 17408 B: 64x136 fp16 A tile
#define BUF  (128 * SPB)         // 34816 B: 128x136 fp16 weight tile

// ---------------- SMEM layout (bytes) ----------------
#define AB_OFF  0                // A operand fp16 (EA tile, later H tile)
#define WB0_OFF ABUF             // weight buffer 0 (W1, then W2 odd chunks)
#define WB1_OFF (ABUF + BUF)     // weight buffer 1 (W2 even chunks; later merge buf)
#define FL_OFF  (ABUF + 2*BUF)   // 87040: float region
#define SA0  0                   // x0*sh0      [64][16]
#define SA1  1024                // x0          [64][16]
#define SA3  2048                // dot/sqrt3   [64][16]
#define SX1  3072                // x1          [64][48]
#define SSH  6144                // sh          [64][4]
#define SDST 6400                // int [64]
#define SSRC 6464                // int [64]
#define SB1  6528                // b1 [128]
#define NFL  6656
#define SMEM_BYTES (FL_OFF + NFL * 4)   // 113664  -> 2 CTAs/SM
#define MG_OFF  WB1_OFF          // merge buffer [64][64] f32 aliases WB1 (dead after ch6)

__device__ float g_acc[NNODES * 64];
__device__ float g_cnt[NNODES];
__device__ __align__(16) unsigned char g_w1s[BUF];       // W1T fp16, n-major padded
__device__ __align__(16) unsigned char g_w2s[8][BUF];    // per N-chunk W2T fp16

// ---------------- helpers ----------------
__device__ __forceinline__ uint32_t smem_u32(const void* p) {
    uint32_t a;
    asm("{ .reg .u64 t; cvta.to.shared.u64 t, %1; cvt.u32.u64 %0, t; }" : "=r"(a) : "l"(p));
    return a;
}
__device__ __forceinline__ void ldsm_x4(uint32_t* r, uint32_t addr) {
    asm volatile("ldmatrix.sync.aligned.m8n8.x4.shared.b16 {%0,%1,%2,%3}, [%4];"
        : "=r"(r[0]), "=r"(r[1]), "=r"(r[2]), "=r"(r[3]) : "r"(addr));
}
__device__ __forceinline__ void mma16816(float* c, const uint32_t* a, const uint32_t* b) {
    asm volatile("mma.sync.aligned.m16n8k16.row.col.f32.f16.f16.f32 "
        "{%0,%1,%2,%3}, {%4,%5,%6,%7}, {%8,%9}, {%0,%1,%2,%3};"
        : "+f"(c[0]), "+f"(c[1]), "+f"(c[2]), "+f"(c[3])
        : "r"(a[0]), "r"(a[1]), "r"(a[2]), "r"(a[3]), "r"(b[0]), "r"(b[1]));
}
__device__ __forceinline__ uint32_t pkh(float a, float b) {
    __half2 h = __floats2half2_rn(a, b);
    return *(uint32_t*)&h;
}
__device__ __forceinline__ void cp16(uint32_t dst, const void* src) {
    asm volatile("cp.async.cg.shared.global [%0], [%1], 16;" :: "r"(dst), "l"(src));
}
#define CP_COMMIT() asm volatile("cp.async.commit_group;" ::: "memory")
#define CP_WAIT(n)  asm volatile("cp.async.wait_group %0;" :: "n"(n) : "memory")

// warp tile m16 x n64 x k128, single pass.
__device__ __forceinline__ void gemm_1p(float acc[8][4],
                                        uint32_t a_base, uint32_t w_base,
                                        uint32_t aoff, uint32_t boff) {
    #pragma unroll
    for (int kp = 0; kp < 4; kp++) {        // k32 per iteration
        uint32_t Am[8];                     // [0..3]=k16lo frag, [4..7]=k16hi frag
        ldsm_x4(Am,     a_base + aoff + kp * 64);
        ldsm_x4(Am + 4, a_base + aoff + kp * 64 + 32);
        #pragma unroll
        for (int nt = 0; nt < 8; nt++) {
            uint32_t Bf[4];
            uint32_t wb = (uint32_t)nt * (8 * SPB) + boff + kp * 64;
            ldsm_x4(Bf, w_base + wb);
            mma16816(acc[nt], Am,     Bf);
            mma16816(acc[nt], Am + 4, Bf + 2);
        }
    }
}

// ---------------- small kernels ----------------
__global__ void zero_kernel() {
    int i = blockIdx.x * blockDim.x + threadIdx.x;
    if (i < NNODES * 64) g_acc[i] = 0.0f;
    else if (i < NNODES * 64 + NNODES) g_cnt[i - NNODES * 64] = 0.0f;
}

__global__ void prep_w1(const float* __restrict__ w1) {
    int t = blockIdx.x * 256 + threadIdx.x;
    if (t >= 128 * 64) return;
    int h = t >> 6, f = (t & 63) * 2;
    uint32_t off = (uint32_t)h * SPB + (uint32_t)f * 2;
    *(uint32_t*)(g_w1s + off) = pkh(w1[f * 128 + h], w1[(f + 1) * 128 + h]);
}

__global__ void prep_w2(const float* __restrict__ w2) {
    int t = blockIdx.x * 256 + threadIdx.x;
    if (t >= 8 * 128 * 64) return;
    int c = t >> 13, n = (t >> 6) & 127, f = (t & 63) * 2;
    int kg = c * 128 + n;
    uint32_t off = (uint32_t)n * SPB + (uint32_t)f * 2;
    *(uint32_t*)(g_w2s[c] + off) = pkh(w2[f * 1024 + kg], w2[(f + 1) * 1024 + kg]);
}

// ---------------- main fused kernel: 256 threads, 4m x 2n warp grid, 64-edge tile ----------------
__global__ void __launch_bounds__(256, 2) fused_kernel(
    const float* __restrict__ x,  const int* __restrict__ ei,
    const float* __restrict__ ea, const float* __restrict__ esh,
    const float* __restrict__ b1, const float* __restrict__ b2)
{
    extern __shared__ unsigned char sm[];
    unsigned char* ABc = sm + AB_OFF;
    float* F   = (float*)(sm + FL_OFF);
    float* Sa0 = F + SA0;
    float* Sa1 = F + SA1;
    float* Sa3 = F + SA3;
    float* Sx1 = F + SX1;
    float* Ssh = F + SSH;
    int* Sdst  = (int*)(F + SDST);
    int* Ssrc  = (int*)(F + SSRC);
    float* b1s = F + SB1;
    float* Mg  = (float*)(sm + MG_OFF);     // [64][64] merge buffer (aliases WB1)

    const int tid = threadIdx.x;
    const int wid = tid >> 5, lid = tid & 31;
    const int e0  = blockIdx.x * TEDGE;
    const uint32_t sb = smem_u32(sm);

    // warp tile geometry: 4 m-groups (m16) x 2 n-halves (n64)
    const int m0 = (wid & 3) * 16;
    const int nq = wid >> 2;                       // 0 or 1
    const int r0 = m0 + (lid >> 2), r1 = r0 + 8;   // the two edge-rows this thread owns
    const int cb = (lid & 3) * 2;
    const uint32_t aoff = (uint32_t)(m0 + (lid & 15)) * SPB + (uint32_t)((lid >> 4) * 8) * 2;
    const uint32_t boff = (uint32_t)(nq * 64 + (lid & 7)) * SPB + (uint32_t)(lid >> 3) * 16;

    // ---- prefetch: G0 = W1 -> WB0, G1 = W2[0] -> WB1 ----
    #pragma unroll
    for (int i = 0; i < 9; i++) {
        uint32_t o = (uint32_t)(tid + i * 256) * 16;
        if (o < BUF) cp16(sb + WB0_OFF + o, g_w1s + o);
    }
    CP_COMMIT();
    #pragma unroll
    for (int i = 0; i < 9; i++) {
        uint32_t o = (uint32_t)(tid + i * 256) * 16;
        if (o < BUF) cp16(sb + WB1_OFF + o, g_w2s[0] + o);
    }
    CP_COMMIT();

    // ---- biases + indices + sh ----
    if (tid < 128) b1s[tid] = b1[tid];
    if (tid < TEDGE) {
        int eg = e0 + tid;
        Ssrc[tid] = ei[eg];
        Sdst[tid] = ei[E_TOTAL + eg];
        float4 s = *(const float4*)(esh + (size_t)eg * 4);
        Ssh[tid*4+0] = s.x; Ssh[tid*4+1] = s.y; Ssh[tid*4+2] = s.z; Ssh[tid*4+3] = s.w;
    }
    __syncthreads();

    // ---- gather x[src] + TP precompute ----
    {
        int e = tid & 63, part = tid >> 6;       // parts 0,1 active; 2,3 idle
        if (part < 2) {
            int src = Ssrc[e];
            const float4* xr = (const float4*)(x + (size_t)src * 64);
            if (part == 0) {
                float sh0 = Ssh[e*4];
                #pragma unroll
                for (int q = 0; q < 4; q++) {
                    float4 xv = xr[q];
                    int u = q * 4;
                    Sa1[e*16+u+0] = xv.x;  Sa0[e*16+u+0] = xv.x * sh0;
                    Sa1[e*16+u+1] = xv.y;  Sa0[e*16+u+1] = xv.y * sh0;
                    Sa1[e*16+u+2] = xv.z;  Sa0[e*16+u+2] = xv.z * sh0;
                    Sa1[e*16+u+3] = xv.w;  Sa0[e*16+u+3] = xv.w * sh0;
                }
            } else {
                float s1x = Ssh[e*4+1], s1y = Ssh[e*4+2], s1z = Ssh[e*4+3];
                float x1l[48];
                #pragma unroll
                for (int q = 0; q < 12; q++) {
                    float4 xv = xr[4 + q];
                    x1l[q*4+0]=xv.x; x1l[q*4+1]=xv.y; x1l[q*4+2]=xv.z; x1l[q*4+3]=xv.w;
                    *(float4*)(Sx1 + e*48 + q*4) = xv;
                }
                #pragma unroll
                for (int u = 0; u < 16; u++) {
                    float d = x1l[u*3]*s1x + x1l[u*3+1]*s1y + x1l[u*3+2]*s1z;
                    Sa3[e*16+u] = d * 0.57735026918962576f;
                }
            }
        }
    }

    // ---- EA tile -> fp16 into A buffer (quarter row per thread) ----
    {
        int r = tid >> 2, q = tid & 3;
        const float4* rowp = (const float4*)(ea + (size_t)(e0 + r) * 128 + q * 32);
        uint32_t* dst = (uint32_t*)(ABc + (uint32_t)r * SPB + (uint32_t)(q * 32) * 2);
        #pragma unroll
        for (int j = 0; j < 8; j++) {
            float4 v = rowp[j];
            dst[j*2]     = pkh(v.x, v.y);
            dst[j*2 + 1] = pkh(v.z, v.w);
        }
    }

    // ---- GEMM1: H = relu(EA @ W1 + b1), single pass ----
    CP_WAIT(1);     // W1 resident (W2[0] may still be in flight)
    __syncthreads();

    float acc[8][4];
    #pragma unroll
    for (int nt = 0; nt < 8; nt++)
        #pragma unroll
        for (int q = 0; q < 4; q++) acc[nt][q] = 0.0f;

    gemm_1p(acc, sb + AB_OFF, sb + WB0_OFF, aoff, boff);
    __syncthreads();   // all warps done with EA + WB0

    // W1 dead: prefetch W2[1] -> WB0 (G2)
    #pragma unroll
    for (int i = 0; i < 9; i++) {
        uint32_t o = (uint32_t)(tid + i * 256) * 16;
        if (o < BUF) cp16(sb + WB0_OFF + o, g_w2s[1] + o);
    }
    CP_COMMIT();

    // writeback H as fp16 (cols nq*64 + nt*8 + cb)
    #pragma unroll
    for (int nt = 0; nt < 8; nt++) {
        int c = nq * 64 + nt * 8 + cb;
        float bb0 = b1s[c], bb1 = b1s[c + 1];
        float h0 = fmaxf(acc[nt][0] + bb0, 0.0f);
        float h1 = fmaxf(acc[nt][1] + bb1, 0.0f);
        float h2 = fmaxf(acc[nt][2] + bb0, 0.0f);
        float h3 = fmaxf(acc[nt][3] + bb1, 0.0f);
        *(uint32_t*)(ABc + (uint32_t)r0 * SPB + (uint32_t)c * 2) = pkh(h0, h1);
        *(uint32_t*)(ABc + (uint32_t)r1 * SPB + (uint32_t)c * 2) = pkh(h2, h3);
    }

    // ---- GEMM2 chunks (single-pass) + TP consumption ----
    float s0[2][4], t1[2][4], o1[2][4][3];
    #pragma unroll
    for (int er = 0; er < 2; er++)
        #pragma unroll
        for (int vi = 0; vi < 4; vi++) {
            s0[er][vi] = 0.0f; t1[er][vi] = 0.0f;
            o1[er][vi][0] = 0.0f; o1[er][vi][1] = 0.0f; o1[er][vi][2] = 0.0f;
        }

    #pragma unroll 1
    for (int ch = 0; ch < 8; ch++) {
        CP_WAIT(1);         // W2[ch] resident (at most W2[ch+1] pending)
        __syncthreads();    // data visible to all; H writes ordered (iter 0)

        #pragma unroll
        for (int nt = 0; nt < 8; nt++)
            #pragma unroll
            for (int q = 0; q < 4; q++) acc[nt][q] = 0.0f;

        uint32_t wbase = (ch & 1) ? (sb + WB0_OFF) : (sb + WB1_OFF);
        gemm_1p(acc, sb + AB_OFF, wbase, aoff, boff);

        // epilogue: wv = acc + b2 ; u = (ch&1)*8 + nq*4 + (nt>>1) ; v = (nt&1)*8 + cb + d
        const int p  = ch >> 1;
        const int ub = (ch & 1) * 8 + nq * 4;
        const float* b2c = b2 + ch * 128 + nq * 64;

        if (p == 2) {
            #pragma unroll
            for (int nt = 0; nt < 8; nt++) {
                int u = ub + (nt >> 1);
                float xa0 = Sx1[r0*48 + u*3 + 0], xb0 = Sx1[r0*48 + u*3 + 1], xc0 = Sx1[r0*48 + u*3 + 2];
                float xa1 = Sx1[r1*48 + u*3 + 0], xb1 = Sx1[r1*48 + u*3 + 1], xc1 = Sx1[r1*48 + u*3 + 2];
                #pragma unroll
                for (int d = 0; d < 2; d++) {
                    float bb = b2c[nt*8 + cb + d];
                    int vi = (nt & 1) * 2 + d;
                    float w0 = acc[nt][d]     + bb;
                    float w1 = acc[nt][2 + d] + bb;
                    o1[0][vi][0] = fmaf(xa0, w0, o1[0][vi][0]);
                    o1[0][vi][1] = fmaf(xb0, w0, o1[0][vi][1]);
                    o1[0][vi][2] = fmaf(xc0, w0, o1[0][vi][2]);
                    o1[1][vi][0] = fmaf(xa1, w1, o1[1][vi][0]);
                    o1[1][vi][1] = fmaf(xb1, w1, o1[1][vi][1]);
                    o1[1][vi][2] = fmaf(xc1, w1, o1[1][vi][2]);
                }
            }
        } else {
            const float* A = (p == 0) ? Sa0 : (p == 1) ? Sa1 : Sa3;
            float a0[4], a1[4];
            #pragma unroll
            for (int u = 0; u < 4; u++) {
                a0[u] = A[r0*16 + ub + u];
                a1[u] = A[r1*16 + ub + u];
            }
            if (p == 1) {
                #pragma unroll
                for (int nt = 0; nt < 8; nt++) {
                    int u = nt >> 1;
                    #pragma unroll
                    for (int d = 0; d < 2; d++) {
                        float bb = b2c[nt*8 + cb + d];
                        int vi = (nt & 1) * 2 + d;
                        t1[0][vi] = fmaf(a0[u], acc[nt][d]     + bb, t1[0][vi]);
                        t1[1][vi] = fmaf(a1[u], acc[nt][2 + d] + bb, t1[1][vi]);
                    }
                }
            } else {
                #pragma unroll
                for (int nt = 0; nt < 8; nt++) {
                    int u = nt >> 1;
                    #pragma unroll
                    for (int d = 0; d < 2; d++) {
                        float bb = b2c[nt*8 + cb + d];
                        int vi = (nt & 1) * 2 + d;
                        s0[0][vi] = fmaf(a0[u], acc[nt][d]     + bb, s0[0][vi]);
                        s0[1][vi] = fmaf(a1[u], acc[nt][2 + d] + bb, s0[1][vi]);
                    }
                }
            }
        }
        __syncthreads();   // all reads of this chunk's buffer complete before refill

        // prefetch W2[ch+2] into the buffer just read (same parity)
        if (ch + 2 <= 7) {
            const unsigned char* s2 = g_w2s[ch + 2];
            uint32_t dsto = (ch & 1) ? WB0_OFF : WB1_OFF;
            #pragma unroll
            for (int i = 0; i < 9; i++) {
                uint32_t o = (uint32_t)(tid + i * 256) * 16;
                if (o < BUF) cp16(sb + dsto + o, s2 + o);
            }
            CP_COMMIT();
        }
    }

    // ---- merge the two n-halves in SMEM (Mg aliases WB1: last read at ch6) ----
    {
        if (nq == 0) {
            #pragma unroll
            for (int er = 0; er < 2; er++) {
                int e = er ? r1 : r0;
                float sh0 = Ssh[e*4+0];
                float s1x = Ssh[e*4+1], s1y = Ssh[e*4+2], s1z = Ssh[e*4+3];
                float* mrow = Mg + e * 64;
                #pragma unroll
                for (int vi = 0; vi < 4; vi++) {
                    int v = cb + (vi >> 1) * 8 + (vi & 1);
                    mrow[v]            = s0[er][vi];
                    mrow[16 + v*3 + 0] = t1[er][vi]*s1x + sh0*o1[er][vi][0];
                    mrow[16 + v*3 + 1] = t1[er][vi]*s1y + sh0*o1[er][vi][1];
                    mrow[16 + v*3 + 2] = t1[er][vi]*s1z + sh0*o1[er][vi][2];
                }
            }
        }
        __syncthreads();
        if (nq == 1) {
            const float alpha = 0.17677669529663689f;  // 1/sqrt(2*16)
            #pragma unroll
            for (int er = 0; er < 2; er++) {
                int e = er ? r1 : r0;
                int dst = Sdst[e];
                float sh0 = Ssh[e*4+0];
                float s1x = Ssh[e*4+1], s1y = Ssh[e*4+2], s1z = Ssh[e*4+3];
                float* mrow = Mg + e * 64;
                float* base = g_acc + (size_t)dst * 64;
                #pragma unroll
                for (int vi = 0; vi < 4; vi++) {
                    int v = cb + (vi >> 1) * 8 + (vi & 1);
                    atomicAdd(base + v, alpha * (s0[er][vi] + mrow[v]));
                    atomicAdd(base + 16 + v*3 + 0,
                        alpha * (t1[er][vi]*s1x + sh0*o1[er][vi][0] + mrow[16 + v*3 + 0]));
                    atomicAdd(base + 16 + v*3 + 1,
                        alpha * (t1[er][vi]*s1y + sh0*o1[er][vi][1] + mrow[16 + v*3 + 1]));
                    atomicAdd(base + 16 + v*3 + 2,
                        alpha * (t1[er][vi]*s1z + sh0*o1[er][vi][2] + mrow[16 + v*3 + 2]));
                }
                if ((lid & 3) == 0) atomicAdd(&g_cnt[dst], 1.0f);
            }
        }
    }
}

__global__ void finalize_kernel(const float* __restrict__ x, float* __restrict__ out) {
    int i = blockIdx.x * blockDim.x + threadIdx.x;
    if (i < NNODES * 64) {
        int node = i >> 6;
        out[i] = g_acc[i] / fmaxf(g_cnt[node], 1.0f) + x[i];
    }
}

extern "C" void kernel_launch(void* const* d_in, const int* in_sizes, int n_in,
                              void* d_out, int out_size)
{
    const float* x   = (const float*)d_in[0];
    const int*   ei  = (const int*)  d_in[1];
    const float* ea  = (const float*)d_in[2];
    const float* esh = (const float*)d_in[3];
    const float* w1  = (const float*)d_in[4];
    const float* b1  = (const float*)d_in[5];
    const float* w2  = (const float*)d_in[6];
    const float* b2  = (const float*)d_in[7];
    float* out = (float*)d_out;

    cudaFuncSetAttribute(fused_kernel,
                         cudaFuncAttributeMaxDynamicSharedMemorySize, SMEM_BYTES);

    int ztot = NNODES * 64 + NNODES;
    zero_kernel<<<(ztot + 255) / 256, 256>>>();
    prep_w1<<<(128 * 64 + 255) / 256, 256>>>(w1);
    prep_w2<<<(8 * 128 * 64 + 255) / 256, 256>>>(w2);
    fused_kernel<<<NBLK, 256, SMEM_BYTES>>>(x, ei, ea, esh, b1, b2);
    finalize_kernel<<<(NNODES * 64 + 255) / 256, 256>>>(x, out);
}

// round 11
// speedup vs baseline: 2.0845x; 1.0007x over previous
#include <cuda_runtime.h>
#include <cuda_fp16.h>
#include <cstdint>

#define E_TOTAL 160000
#define NNODES  10000
#define NBLK    2500
#define TEDGE   64

#define SP   136                 // padded row stride (fp16 elems)
#define SPB  272                 // row stride bytes
#define ABUF (64 * SPB)          // 17408 B: 64x136 fp16 A tile
#define BUF  (128 * SPB)         // 34816 B: 128x136 fp16 weight tile

// ---------------- SMEM layout (bytes) ----------------
#define AB_OFF  0                // A operand fp16 (EA tile, later H tile)
#define WB0_OFF ABUF             // weight buffer 0 (W1, then W2 odd chunks)
#define WB1_OFF (ABUF + BUF)     // weight buffer 1 (W2 even chunks; later merge buf)
#define FL_OFF  (ABUF + 2*BUF)   // 87040: float region
#define SA0  0                   // x0*sh0      [64][16]
#define SA1  1024                // x0          [64][16]
#define SA3  2048                // dot/sqrt3   [64][16]
#define SX1  3072                // x1          [64][48]
#define SSH  6144                // sh          [64][4]
#define SDST 6400                // int [64]
#define SSRC 6464                // int [64]
#define SB1  6528                // b1 [128]
#define NFL  6656
#define SMEM_BYTES (FL_OFF + NFL * 4)   // 113664  -> 2 CTAs/SM
#define MG_OFF  WB1_OFF          // merge buffer [64][64] f32 aliases WB1 (dead after ch6)

__device__ float g_acc[NNODES * 64];
__device__ float g_cnt[NNODES];
__device__ __align__(16) unsigned char g_w1s[BUF];       // W1T fp16, n-major padded
__device__ __align__(16) unsigned char g_w2s[8][BUF];    // per N-chunk W2T fp16

// ---------------- helpers ----------------
__device__ __forceinline__ uint32_t smem_u32(const void* p) {
    uint32_t a;
    asm("{ .reg .u64 t; cvta.to.shared.u64 t, %1; cvt.u32.u64 %0, t; }" : "=r"(a) : "l"(p));
    return a;
}
__device__ __forceinline__ void ldsm_x4(uint32_t* r, uint32_t addr) {
    asm volatile("ldmatrix.sync.aligned.m8n8.x4.shared.b16 {%0,%1,%2,%3}, [%4];"
        : "=r"(r[0]), "=r"(r[1]), "=r"(r[2]), "=r"(r[3]) : "r"(addr));
}
__device__ __forceinline__ void mma16816(float* c, const uint32_t* a, const uint32_t* b) {
    asm volatile("mma.sync.aligned.m16n8k16.row.col.f32.f16.f16.f32 "
        "{%0,%1,%2,%3}, {%4,%5,%6,%7}, {%8,%9}, {%0,%1,%2,%3};"
        : "+f"(c[0]), "+f"(c[1]), "+f"(c[2]), "+f"(c[3])
        : "r"(a[0]), "r"(a[1]), "r"(a[2]), "r"(a[3]), "r"(b[0]), "r"(b[1]));
}
__device__ __forceinline__ uint32_t pkh(float a, float b) {
    __half2 h = __floats2half2_rn(a, b);
    return *(uint32_t*)&h;
}
__device__ __forceinline__ void cp16(uint32_t dst, const void* src) {
    asm volatile("cp.async.cg.shared.global [%0], [%1], 16;" :: "r"(dst), "l"(src));
}
#define CP_COMMIT() asm volatile("cp.async.commit_group;" ::: "memory")
#define CP_WAIT(n)  asm volatile("cp.async.wait_group %0;" :: "n"(n) : "memory")

// warp tile m16 x n64 x k128, single pass.
__device__ __forceinline__ void gemm_1p(float acc[8][4],
                                        uint32_t a_base, uint32_t w_base,
                                        uint32_t aoff, uint32_t boff) {
    #pragma unroll
    for (int kp = 0; kp < 4; kp++) {        // k32 per iteration
        uint32_t Am[8];                     // [0..3]=k16lo frag, [4..7]=k16hi frag
        ldsm_x4(Am,     a_base + aoff + kp * 64);
        ldsm_x4(Am + 4, a_base + aoff + kp * 64 + 32);
        #pragma unroll
        for (int nt = 0; nt < 8; nt++) {
            uint32_t Bf[4];
            uint32_t wb = (uint32_t)nt * (8 * SPB) + boff + kp * 64;
            ldsm_x4(Bf, w_base + wb);
            mma16816(acc[nt], Am,     Bf);
            mma16816(acc[nt], Am + 4, Bf + 2);
        }
    }
}

// ---------------- small kernels ----------------
__global__ void zero_kernel() {
    int i = blockIdx.x * blockDim.x + threadIdx.x;
    if (i < NNODES * 64) g_acc[i] = 0.0f;
    else if (i < NNODES * 64 + NNODES) g_cnt[i - NNODES * 64] = 0.0f;
}

__global__ void prep_w1(const float* __restrict__ w1) {
    int t = blockIdx.x * 256 + threadIdx.x;
    if (t >= 128 * 64) return;
    int h = t >> 6, f = (t & 63) * 2;
    uint32_t off = (uint32_t)h * SPB + (uint32_t)f * 2;
    *(uint32_t*)(g_w1s + off) = pkh(w1[f * 128 + h], w1[(f + 1) * 128 + h]);
}

__global__ void prep_w2(const float* __restrict__ w2) {
    int t = blockIdx.x * 256 + threadIdx.x;
    if (t >= 8 * 128 * 64) return;
    int c = t >> 13, n = (t >> 6) & 127, f = (t & 63) * 2;
    int kg = c * 128 + n;
    uint32_t off = (uint32_t)n * SPB + (uint32_t)f * 2;
    *(uint32_t*)(g_w2s[c] + off) = pkh(w2[f * 1024 + kg], w2[(f + 1) * 1024 + kg]);
}

// ---------------- main fused kernel: 256 threads, 4m x 2n warp grid, 64-edge tile ----------------
__global__ void __launch_bounds__(256, 2) fused_kernel(
    const float* __restrict__ x,  const int* __restrict__ ei,
    const float* __restrict__ ea, const float* __restrict__ esh,
    const float* __restrict__ b1, const float* __restrict__ b2)
{
    extern __shared__ unsigned char sm[];
    unsigned char* ABc = sm + AB_OFF;
    float* F   = (float*)(sm + FL_OFF);
    float* Sa0 = F + SA0;
    float* Sa1 = F + SA1;
    float* Sa3 = F + SA3;
    float* Sx1 = F + SX1;
    float* Ssh = F + SSH;
    int* Sdst  = (int*)(F + SDST);
    int* Ssrc  = (int*)(F + SSRC);
    float* b1s = F + SB1;
    float* Mg  = (float*)(sm + MG_OFF);     // [64][64] merge buffer (aliases WB1)

    const int tid = threadIdx.x;
    const int wid = tid >> 5, lid = tid & 31;
    const int e0  = blockIdx.x * TEDGE;
    const uint32_t sb = smem_u32(sm);

    // warp tile geometry: 4 m-groups (m16) x 2 n-halves (n64)
    const int m0 = (wid & 3) * 16;
    const int nq = wid >> 2;                       // 0 or 1
    const int r0 = m0 + (lid >> 2), r1 = r0 + 8;   // the two edge-rows this thread owns
    const int cb = (lid & 3) * 2;
    const uint32_t aoff = (uint32_t)(m0 + (lid & 15)) * SPB + (uint32_t)((lid >> 4) * 8) * 2;
    const uint32_t boff = (uint32_t)(nq * 64 + (lid & 7)) * SPB + (uint32_t)(lid >> 3) * 16;

    // ---- prefetch: G0 = W1 -> WB0, G1 = W2[0] -> WB1 ----
    #pragma unroll
    for (int i = 0; i < 9; i++) {
        uint32_t o = (uint32_t)(tid + i * 256) * 16;
        if (o < BUF) cp16(sb + WB0_OFF + o, g_w1s + o);
    }
    CP_COMMIT();
    #pragma unroll
    for (int i = 0; i < 9; i++) {
        uint32_t o = (uint32_t)(tid + i * 256) * 16;
        if (o < BUF) cp16(sb + WB1_OFF + o, g_w2s[0] + o);
    }
    CP_COMMIT();

    // ---- biases + indices + sh ----
    if (tid < 128) b1s[tid] = b1[tid];
    if (tid < TEDGE) {
        int eg = e0 + tid;
        Ssrc[tid] = ei[eg];
        Sdst[tid] = ei[E_TOTAL + eg];
        float4 s = *(const float4*)(esh + (size_t)eg * 4);
        Ssh[tid*4+0] = s.x; Ssh[tid*4+1] = s.y; Ssh[tid*4+2] = s.z; Ssh[tid*4+3] = s.w;
    }
    __syncthreads();

    // ---- gather x[src] + TP precompute ----
    {
        int e = tid & 63, part = tid >> 6;       // parts 0,1 active; 2,3 idle
        if (part < 2) {
            int src = Ssrc[e];
            const float4* xr = (const float4*)(x + (size_t)src * 64);
            if (part == 0) {
                float sh0 = Ssh[e*4];
                #pragma unroll
                for (int q = 0; q < 4; q++) {
                    float4 xv = xr[q];
                    int u = q * 4;
                    Sa1[e*16+u+0] = xv.x;  Sa0[e*16+u+0] = xv.x * sh0;
                    Sa1[e*16+u+1] = xv.y;  Sa0[e*16+u+1] = xv.y * sh0;
                    Sa1[e*16+u+2] = xv.z;  Sa0[e*16+u+2] = xv.z * sh0;
                    Sa1[e*16+u+3] = xv.w;  Sa0[e*16+u+3] = xv.w * sh0;
                }
            } else {
                float s1x = Ssh[e*4+1], s1y = Ssh[e*4+2], s1z = Ssh[e*4+3];
                float x1l[48];
                #pragma unroll
                for (int q = 0; q < 12; q++) {
                    float4 xv = xr[4 + q];
                    x1l[q*4+0]=xv.x; x1l[q*4+1]=xv.y; x1l[q*4+2]=xv.z; x1l[q*4+3]=xv.w;
                    *(float4*)(Sx1 + e*48 + q*4) = xv;
                }
                #pragma unroll
                for (int u = 0; u < 16; u++) {
                    float d = x1l[u*3]*s1x + x1l[u*3+1]*s1y + x1l[u*3+2]*s1z;
                    Sa3[e*16+u] = d * 0.57735026918962576f;
                }
            }
        }
    }

    // ---- EA tile -> fp16 into A buffer (quarter row per thread) ----
    {
        int r = tid >> 2, q = tid & 3;
        const float4* rowp = (const float4*)(ea + (size_t)(e0 + r) * 128 + q * 32);
        uint32_t* dst = (uint32_t*)(ABc + (uint32_t)r * SPB + (uint32_t)(q * 32) * 2);
        #pragma unroll
        for (int j = 0; j < 8; j++) {
            float4 v = rowp[j];
            dst[j*2]     = pkh(v.x, v.y);
            dst[j*2 + 1] = pkh(v.z, v.w);
        }
    }

    // ---- GEMM1: H = relu(EA @ W1 + b1), single pass ----
    CP_WAIT(1);     // W1 resident (W2[0] may still be in flight)
    __syncthreads();

    float acc[8][4];
    #pragma unroll
    for (int nt = 0; nt < 8; nt++)
        #pragma unroll
        for (int q = 0; q < 4; q++) acc[nt][q] = 0.0f;

    gemm_1p(acc, sb + AB_OFF, sb + WB0_OFF, aoff, boff);
    __syncthreads();   // all warps done with EA + WB0

    // W1 dead: prefetch W2[1] -> WB0 (G2)
    #pragma unroll
    for (int i = 0; i < 9; i++) {
        uint32_t o = (uint32_t)(tid + i * 256) * 16;
        if (o < BUF) cp16(sb + WB0_OFF + o, g_w2s[1] + o);
    }
    CP_COMMIT();

    // writeback H as fp16 (cols nq*64 + nt*8 + cb)
    #pragma unroll
    for (int nt = 0; nt < 8; nt++) {
        int c = nq * 64 + nt * 8 + cb;
        float bb0 = b1s[c], bb1 = b1s[c + 1];
        float h0 = fmaxf(acc[nt][0] + bb0, 0.0f);
        float h1 = fmaxf(acc[nt][1] + bb1, 0.0f);
        float h2 = fmaxf(acc[nt][2] + bb0, 0.0f);
        float h3 = fmaxf(acc[nt][3] + bb1, 0.0f);
        *(uint32_t*)(ABc + (uint32_t)r0 * SPB + (uint32_t)c * 2) = pkh(h0, h1);
        *(uint32_t*)(ABc + (uint32_t)r1 * SPB + (uint32_t)c * 2) = pkh(h2, h3);
    }

    // ---- GEMM2 chunks (single-pass) + TP consumption ----
    float s0[2][4], t1[2][4], o1[2][4][3];
    #pragma unroll
    for (int er = 0; er < 2; er++)
        #pragma unroll
        for (int vi = 0; vi < 4; vi++) {
            s0[er][vi] = 0.0f; t1[er][vi] = 0.0f;
            o1[er][vi][0] = 0.0f; o1[er][vi][1] = 0.0f; o1[er][vi][2] = 0.0f;
        }

    #pragma unroll 1
    for (int ch = 0; ch < 8; ch++) {
        CP_WAIT(1);         // W2[ch] resident (at most W2[ch+1] pending)
        __syncthreads();    // data visible to all; H writes ordered (iter 0)

        #pragma unroll
        for (int nt = 0; nt < 8; nt++)
            #pragma unroll
            for (int q = 0; q < 4; q++) acc[nt][q] = 0.0f;

        uint32_t wbase = (ch & 1) ? (sb + WB0_OFF) : (sb + WB1_OFF);
        gemm_1p(acc, sb + AB_OFF, wbase, aoff, boff);

        // epilogue: wv = acc + b2 ; u = (ch&1)*8 + nq*4 + (nt>>1) ; v = (nt&1)*8 + cb + d
        const int p  = ch >> 1;
        const int ub = (ch & 1) * 8 + nq * 4;
        const float* b2c = b2 + ch * 128 + nq * 64;

        if (p == 2) {
            #pragma unroll
            for (int nt = 0; nt < 8; nt++) {
                int u = ub + (nt >> 1);
                float xa0 = Sx1[r0*48 + u*3 + 0], xb0 = Sx1[r0*48 + u*3 + 1], xc0 = Sx1[r0*48 + u*3 + 2];
                float xa1 = Sx1[r1*48 + u*3 + 0], xb1 = Sx1[r1*48 + u*3 + 1], xc1 = Sx1[r1*48 + u*3 + 2];
                #pragma unroll
                for (int d = 0; d < 2; d++) {
                    float bb = b2c[nt*8 + cb + d];
                    int vi = (nt & 1) * 2 + d;
                    float w0 = acc[nt][d]     + bb;
                    float w1 = acc[nt][2 + d] + bb;
                    o1[0][vi][0] = fmaf(xa0, w0, o1[0][vi][0]);
                    o1[0][vi][1] = fmaf(xb0, w0, o1[0][vi][1]);
                    o1[0][vi][2] = fmaf(xc0, w0, o1[0][vi][2]);
                    o1[1][vi][0] = fmaf(xa1, w1, o1[1][vi][0]);
                    o1[1][vi][1] = fmaf(xb1, w1, o1[1][vi][1]);
                    o1[1][vi][2] = fmaf(xc1, w1, o1[1][vi][2]);
                }
            }
        } else {
            const float* A = (p == 0) ? Sa0 : (p == 1) ? Sa1 : Sa3;
            float a0[4], a1[4];
            #pragma unroll
            for (int u = 0; u < 4; u++) {
                a0[u] = A[r0*16 + ub + u];
                a1[u] = A[r1*16 + ub + u];
            }
            if (p == 1) {
                #pragma unroll
                for (int nt = 0; nt < 8; nt++) {
                    int u = nt >> 1;
                    #pragma unroll
                    for (int d = 0; d < 2; d++) {
                        float bb = b2c[nt*8 + cb + d];
                        int vi = (nt & 1) * 2 + d;
                        t1[0][vi] = fmaf(a0[u], acc[nt][d]     + bb, t1[0][vi]);
                        t1[1][vi] = fmaf(a1[u], acc[nt][2 + d] + bb, t1[1][vi]);
                    }
                }
            } else {
                #pragma unroll
                for (int nt = 0; nt < 8; nt++) {
                    int u = nt >> 1;
                    #pragma unroll
                    for (int d = 0; d < 2; d++) {
                        float bb = b2c[nt*8 + cb + d];
                        int vi = (nt & 1) * 2 + d;
                        s0[0][vi] = fmaf(a0[u], acc[nt][d]     + bb, s0[0][vi]);
                        s0[1][vi] = fmaf(a1[u], acc[nt][2 + d] + bb, s0[1][vi]);
                    }
                }
            }
        }
        __syncthreads();   // all reads of this chunk's buffer complete before refill

        // prefetch W2[ch+2] into the buffer just read (same parity)
        if (ch + 2 <= 7) {
            const unsigned char* s2 = g_w2s[ch + 2];
            uint32_t dsto = (ch & 1) ? WB0_OFF : WB1_OFF;
            #pragma unroll
            for (int i = 0; i < 9; i++) {
                uint32_t o = (uint32_t)(tid + i * 256) * 16;
                if (o < BUF) cp16(sb + dsto + o, s2 + o);
            }
            CP_COMMIT();
        }
    }

    // ---- merge the two n-halves in SMEM (Mg aliases WB1: last read at ch6) ----
    {
        if (nq == 0) {
            #pragma unroll
            for (int er = 0; er < 2; er++) {
                int e = er ? r1 : r0;
                float sh0 = Ssh[e*4+0];
                float s1x = Ssh[e*4+1], s1y = Ssh[e*4+2], s1z = Ssh[e*4+3];
                float* mrow = Mg + e * 64;
                #pragma unroll
                for (int vi = 0; vi < 4; vi++) {
                    int v = cb + (vi >> 1) * 8 + (vi & 1);
                    mrow[v]            = s0[er][vi];
                    mrow[16 + v*3 + 0] = t1[er][vi]*s1x + sh0*o1[er][vi][0];
                    mrow[16 + v*3 + 1] = t1[er][vi]*s1y + sh0*o1[er][vi][1];
                    mrow[16 + v*3 + 2] = t1[er][vi]*s1z + sh0*o1[er][vi][2];
                }
            }
        }
        __syncthreads();
        if (nq == 1) {
            const float alpha = 0.17677669529663689f;  // 1/sqrt(2*16)
            #pragma unroll
            for (int er = 0; er < 2; er++) {
                int e = er ? r1 : r0;
                int dst = Sdst[e];
                float sh0 = Ssh[e*4+0];
                float s1x = Ssh[e*4+1], s1y = Ssh[e*4+2], s1z = Ssh[e*4+3];
                float* mrow = Mg + e * 64;
                float* base = g_acc + (size_t)dst * 64;
                #pragma unroll
                for (int vi = 0; vi < 4; vi++) {
                    int v = cb + (vi >> 1) * 8 + (vi & 1);
                    atomicAdd(base + v, alpha * (s0[er][vi] + mrow[v]));
                    atomicAdd(base + 16 + v*3 + 0,
                        alpha * (t1[er][vi]*s1x + sh0*o1[er][vi][0] + mrow[16 + v*3 + 0]));
                    atomicAdd(base + 16 + v*3 + 1,
                        alpha * (t1[er][vi]*s1y + sh0*o1[er][vi][1] + mrow[16 + v*3 + 1]));
                    atomicAdd(base + 16 + v*3 + 2,
                        alpha * (t1[er][vi]*s1z + sh0*o1[er][vi][2] + mrow[16 + v*3 + 2]));
                }
                if ((lid & 3) == 0) atomicAdd(&g_cnt[dst], 1.0f);
            }
        }
    }
}

__global__ void finalize_kernel(const float* __restrict__ x, float* __restrict__ out) {
    int i = blockIdx.x * blockDim.x + threadIdx.x;
    if (i < NNODES * 64) {
        int node = i >> 6;
        out[i] = g_acc[i] / fmaxf(g_cnt[node], 1.0f) + x[i];
    }
}

extern "C" void kernel_launch(void* const* d_in, const int* in_sizes, int n_in,
                              void* d_out, int out_size)
{
    const float* x   = (const float*)d_in[0];
    const int*   ei  = (const int*)  d_in[1];
    const float* ea  = (const float*)d_in[2];
    const float* esh = (const float*)d_in[3];
    const float* w1  = (const float*)d_in[4];
    const float* b1  = (const float*)d_in[5];
    const float* w2  = (const float*)d_in[6];
    const float* b2  = (const float*)d_in[7];
    float* out = (float*)d_out;

    cudaFuncSetAttribute(fused_kernel,
                         cudaFuncAttributeMaxDynamicSharedMemorySize, SMEM_BYTES);

    int ztot = NNODES * 64 + NNODES;
    zero_kernel<<<(ztot + 255) / 256, 256>>>();
    prep_w1<<<(128 * 64 + 255) / 256, 256>>>(w1);
    prep_w2<<<(8 * 128 * 64 + 255) / 256, 256>>>(w2);
    fused_kernel<<<NBLK, 256, SMEM_BYTES>>>(x, ei, ea, esh, b1, b2);
    finalize_kernel<<<(NNODES * 64 + 255) / 256, 256>>>(x, out);
}